// round 1
// baseline (speedup 1.0000x reference)
#include <cuda_runtime.h>
#include <math.h>

// Problem dims
#define B 128
#define S 4096
#define D 256   // Q_DIM == V_DIM
#define U 128   // UNITS

// Scratch (no cudaMalloc allowed)
__device__ float g_qpb[B * U];      // query@W1 + b1 + b2
__device__ float g_score[B * S];    // pre-softmax scores

// ---------------------------------------------------------------------------
// K1: q_proj[b,u] = query[b,:]@W1[:,u] + b1[u] + b2[u]   (fold b2 in here)
// ---------------------------------------------------------------------------
__global__ void qproj_kernel(const float* __restrict__ query,
                             const float* __restrict__ W1,
                             const float* __restrict__ b1,
                             const float* __restrict__ b2) {
    int b = blockIdx.x;
    int u = threadIdx.x;        // 128 threads
    __shared__ float sq[D];
    for (int i = threadIdx.x; i < D; i += blockDim.x)
        sq[i] = query[b * D + i];
    __syncthreads();
    float acc = b1[u] + b2[u];
    #pragma unroll 8
    for (int d = 0; d < D; d++)
        acc += sq[d] * W1[d * U + u];
    g_qpb[b * U + u] = acc;
}

// ---------------------------------------------------------------------------
// K2: scores. One block = one batch x 1024-seq chunk. 256 threads.
//   smem: full W2 [256][128] (128KB) + values sub-tile [64][260] + qpb + Wv.
//   Thread tile: 4 seq x 8 units (units = {4tu..4tu+3} U {64+4tu..64+4tu+3}
//   so the two float4 W2 loads are bank-conflict-free).
// ---------------------------------------------------------------------------
#define CHUNK 1024
#define SUBT 64
#define VPAD 260   // 64-row values tile padded to 260 floats/row (16B-aligned rows)

__global__ __launch_bounds__(256, 1)
void score_kernel(const float* __restrict__ values,
                  const float* __restrict__ W2,
                  const float* __restrict__ Wv,
                  const float* __restrict__ bv) {
    extern __shared__ float sm[];
    float* sW2 = sm;                    // D*U = 32768 floats
    float* sV  = sm + D * U;            // SUBT*VPAD = 16640 floats
    float* sQ  = sV + SUBT * VPAD;      // U floats
    float* sWv = sQ + U;                // U floats

    const int tid = threadIdx.x;
    const int tu  = tid & 15;
    const int ts  = tid >> 4;
    const int b      = blockIdx.y;
    const int s_base = blockIdx.x * CHUNK;

    // Stage W2 (float4, coalesced)
    {
        const float4* g = reinterpret_cast<const float4*>(W2);
        float4* d4 = reinterpret_cast<float4*>(sW2);
        for (int i = tid; i < (D * U) / 4; i += 256) d4[i] = g[i];
    }
    for (int i = tid; i < U; i += 256) {
        sQ[i]  = g_qpb[b * U + i];
        sWv[i] = Wv[i];
    }
    const float bvv = bv[0];

    const float* vbase = values + (size_t)b * S * D + (size_t)s_base * D;

    for (int sub = 0; sub < CHUNK / SUBT; sub++) {
        __syncthreads();   // previous compute done (also first-iter ordering)
        // Stage values sub-tile [64 s][256 d] into padded smem rows
        {
            const float4* g = reinterpret_cast<const float4*>(vbase + (size_t)sub * SUBT * D);
            for (int i = tid; i < SUBT * (D / 4); i += 256) {
                int s  = i / (D / 4);
                int dq = i % (D / 4);
                *reinterpret_cast<float4*>(&sV[s * VPAD + 4 * dq]) = g[i];
            }
        }
        __syncthreads();

        float acc[32];
        #pragma unroll
        for (int k = 0; k < 32; k++) acc[k] = 0.0f;

        const float* vr = &sV[(4 * ts) * VPAD];

        #pragma unroll 4
        for (int d = 0; d < D; d++) {
            float4 wA = *reinterpret_cast<const float4*>(&sW2[d * U + 4 * tu]);
            float4 wB = *reinterpret_cast<const float4*>(&sW2[d * U + 64 + 4 * tu]);
            float w[8] = {wA.x, wA.y, wA.z, wA.w, wB.x, wB.y, wB.z, wB.w};
            float v[4];
            v[0] = vr[d];
            v[1] = vr[VPAD + d];
            v[2] = vr[2 * VPAD + d];
            v[3] = vr[3 * VPAD + d];
            #pragma unroll
            for (int i = 0; i < 4; i++)
                #pragma unroll
                for (int j = 0; j < 8; j++)
                    acc[i * 8 + j] += v[i] * w[j];
        }

        // Epilogue: score[s] = sum_u tanh(acc + qpb[u]) * Wv[u] + bv
        #pragma unroll
        for (int i = 0; i < 4; i++) {
            float p = 0.0f;
            #pragma unroll
            for (int j = 0; j < 8; j++) {
                int u = (j < 4) ? (4 * tu + j) : (64 + 4 * tu + (j - 4));
                p += tanhf(acc[i * 8 + j] + sQ[u]) * sWv[u];
            }
            #pragma unroll
            for (int off = 8; off > 0; off >>= 1)
                p += __shfl_down_sync(0xffffffffu, p, off, 16);
            if (tu == 0)
                g_score[b * S + s_base + sub * SUBT + ts * 4 + i] = p + bvv;
        }
    }
}

// ---------------------------------------------------------------------------
// K3: softmax over seq per batch, writes normalized weights to d_out[B*D ...]
// ---------------------------------------------------------------------------
__global__ void softmax_kernel(float* __restrict__ out_w) {
    int b = blockIdx.x;
    int tid = threadIdx.x;   // 256
    __shared__ float red[256];
    const float* sc = g_score + b * S;

    float m = -1e30f;
    for (int i = tid; i < S; i += 256) m = fmaxf(m, sc[i]);
    red[tid] = m;
    __syncthreads();
    for (int off = 128; off > 0; off >>= 1) {
        if (tid < off) red[tid] = fmaxf(red[tid], red[tid + off]);
        __syncthreads();
    }
    m = red[0];
    __syncthreads();

    float sum = 0.0f;
    for (int i = tid; i < S; i += 256) sum += expf(sc[i] - m);
    red[tid] = sum;
    __syncthreads();
    for (int off = 128; off > 0; off >>= 1) {
        if (tid < off) red[tid] += red[tid + off];
        __syncthreads();
    }
    float inv = 1.0f / red[0];

    float* w = out_w + b * S;
    for (int i = tid; i < S; i += 256)
        w[i] = expf(sc[i] - m) * inv;
}

// ---------------------------------------------------------------------------
// K4: context[b,d] = sum_s w[b,s] * values[b,s,d]
// ---------------------------------------------------------------------------
__global__ __launch_bounds__(256)
void context_kernel(const float* __restrict__ values,
                    const float* __restrict__ weights,
                    float* __restrict__ ctx) {
    int b = blockIdx.x;
    int t = threadIdx.x;   // 256 == D
    __shared__ float sw_[S];
    for (int i = t; i < S; i += 256) sw_[i] = weights[b * S + i];
    __syncthreads();

    const float* vp = values + (size_t)b * S * D + t;
    float acc = 0.0f;
    for (int s = 0; s < S; s += 8) {
        #pragma unroll
        for (int k = 0; k < 8; k++)
            acc += sw_[s + k] * vp[(size_t)(s + k) * D];
    }
    ctx[b * D + t] = acc;
}

// ---------------------------------------------------------------------------
extern "C" void kernel_launch(void* const* d_in, const int* in_sizes, int n_in,
                              void* d_out, int out_size) {
    const float* query  = (const float*)d_in[0];
    const float* values = (const float*)d_in[1];
    const float* W1     = (const float*)d_in[2];
    const float* b1     = (const float*)d_in[3];
    const float* W2     = (const float*)d_in[4];
    const float* b2     = (const float*)d_in[5];
    const float* Wv     = (const float*)d_in[6];
    const float* bv     = (const float*)d_in[7];

    float* out  = (float*)d_out;
    float* ctx  = out;            // [B, D]
    float* wout = out + B * D;    // [B, S, 1]

    // K2 smem: W2 + padded values tile + qpb + Wv
    const size_t smem2 = (size_t)(D * U + SUBT * VPAD + 2 * U) * sizeof(float);
    cudaFuncSetAttribute(score_kernel, cudaFuncAttributeMaxDynamicSharedMemorySize,
                         (int)smem2);

    qproj_kernel<<<B, U>>>(query, W1, b1, b2);
    dim3 g2(S / CHUNK, B);
    score_kernel<<<g2, 256, smem2>>>(values, W2, Wv, bv);
    softmax_kernel<<<B, 256>>>(wout);
    context_kernel<<<B, 256>>>(values, wout, ctx);
}

// round 4
// speedup vs baseline: 3.0234x; 3.0234x over previous
#include <cuda_runtime.h>
#include <cstdint>
#include <math.h>

#define B_ 128
#define S_ 4096
#define D_ 256
#define U_ 128

// ---------------- device scratch (no allocs allowed) ----------------
__device__ float g_qpb[B_ * U_];                 // q@W1 + b1 + b2
__device__ float g_score[B_ * S_];               // pre-softmax scores
#define CSPLIT 8
__device__ float g_cpart[CSPLIT * B_ * D_];      // context partials

// ---------------- helpers ----------------
__device__ __forceinline__ uint32_t smem_u32(const void* p) {
    uint32_t a;
    asm("{ .reg .u64 t; cvta.to.shared.u64 t, %1; cvt.u32.u64 %0, t; }" : "=r"(a) : "l"(p));
    return a;
}
__device__ __forceinline__ void cp_async16(uint32_t dst, const void* src) {
    asm volatile("cp.async.cg.shared.global [%0], [%1], 16;" :: "r"(dst), "l"(src));
}
#define CP_COMMIT() asm volatile("cp.async.commit_group;" ::: "memory")
#define CP_WAIT0()  asm volatile("cp.async.wait_group 0;" ::: "memory")

__device__ __forceinline__ uint32_t rna_tf32(float f) {
    uint32_t r;
    asm("cvt.rna.tf32.f32 %0, %1;" : "=r"(r) : "f"(f));
    return r;
}

// mma.sync m16n8k8 tf32: D += A*B  (row.col)
__device__ __forceinline__ void mma_tf32(float* d, const uint32_t* a,
                                         uint32_t b0, uint32_t b1) {
    asm volatile(
        "mma.sync.aligned.m16n8k8.row.col.f32.tf32.tf32.f32 "
        "{%0,%1,%2,%3}, {%4,%5,%6,%7}, {%8,%9}, {%0,%1,%2,%3};"
        : "+f"(d[0]), "+f"(d[1]), "+f"(d[2]), "+f"(d[3])
        : "r"(a[0]), "r"(a[1]), "r"(a[2]), "r"(a[3]), "r"(b0), "r"(b1));
}

__device__ __forceinline__ float tanh_fast(float x) {
    float ax = fabsf(x);
    float e  = __expf(ax + ax);
    float t  = 1.0f - __fdividef(2.0f, e + 1.0f);
    return copysignf(t, x);
}

// ---------------------------------------------------------------------------
// K1: qpb[b,u] = query[b,:]@W1[:,u] + b1[u] + b2[u]
// ---------------------------------------------------------------------------
__global__ void qproj_kernel(const float* __restrict__ query,
                             const float* __restrict__ W1,
                             const float* __restrict__ b1,
                             const float* __restrict__ b2) {
    int b = blockIdx.x;
    int u = threadIdx.x;
    __shared__ float sq[D_];
    for (int i = threadIdx.x; i < D_; i += blockDim.x) sq[i] = query[b * D_ + i];
    __syncthreads();
    float acc = b1[u] + b2[u];
    #pragma unroll 8
    for (int d = 0; d < D_; d++) acc += sq[d] * W1[d * U_ + u];
    g_qpb[b * U_ + u] = acc;
}

// ---------------------------------------------------------------------------
// K2: score kernel via mma.sync tf32 (HMMA path; tcgen05 unavailable on the
//     harness's sm_103 PTX target).
//   Grid = 1024 CTAs: b = bid>>3, s0 = (bid&7)*512. Each CTA: 4 tiles of 128 seq.
//   256 threads = 8 warps, warp grid 4(M)x2(N), warp tile 32 seq x 64 units.
//   K=256 staged as 4 chunks of 64, double-buffered cp.async.
//   SMEM floats: sQ[128] | sWv[128] | sred[256] | A 2x(128x68) | B 256x136
// ---------------------------------------------------------------------------
#define ASTRIDE 68
#define BSTRIDE 136
#define A_BUF_F (128 * ASTRIDE)                 // 8704 floats per buffer
#define OFF_A_F 512
#define OFF_B_F (OFF_A_F + 2 * A_BUF_F)         // 17920
#define SMEM_F  (OFF_B_F + D_ * BSTRIDE)        // 52736 floats
#define SMEM_SC (SMEM_F * 4)                    // 210944 bytes

#define NTILE  4
#define NCHUNK 16   // NTILE * 4

__global__ __launch_bounds__(256, 1)
void score_mma_kernel(const float* __restrict__ values,
                      const float* __restrict__ W2,
                      const float* __restrict__ Wv,
                      const float* __restrict__ bv) {
    extern __shared__ float sm[];
    float* sQ   = sm;
    float* sWv  = sm + 128;
    float* sred = sm + 256;
    float* sA   = sm + OFF_A_F;
    float* sB   = sm + OFF_B_F;

    const int tid  = threadIdx.x;
    const int wid  = tid >> 5;
    const int lane = tid & 31;
    const int g    = lane >> 2;     // group id (row within frag)
    const int q    = lane & 3;      // thread-in-group (col within frag)
    const int wm   = wid >> 1;      // warp M index (0..3)
    const int wn   = wid & 1;       // warp N index (0..1)

    const int b  = blockIdx.x >> 3;
    const int s0 = (blockIdx.x & 7) * 512;
    const float bvv = bv[0];

    // ---- prologue: start first A chunk immediately ----
    auto issue = [&](int gc) {
        int mm = gc >> 2, kc = gc & 3;
        const float* src = values + ((size_t)(b * S_ + s0 + mm * 128)) * D_ + kc * 64;
        float* dst = sA + (gc & 1) * A_BUF_F;
        #pragma unroll
        for (int kk = 0; kk < 8; kk++) {
            int idx = tid + kk * 256;
            int row = idx >> 4, f4 = idx & 15;
            cp_async16(smem_u32(dst + row * ASTRIDE + f4 * 4),
                       src + (size_t)row * D_ + f4 * 4);
        }
        CP_COMMIT();
    };
    issue(0);

    // ---- stage B = W2 [k][u] tf32-rounded, padded stride 136 ----
    for (int idx = tid; idx < D_ * U_; idx += 256) {
        int k = idx >> 7, u = idx & 127;
        sB[k * BSTRIDE + u] = __uint_as_float(rna_tf32(W2[idx]));
    }
    for (int i = tid; i < U_; i += 256) {
        sQ[i]  = g_qpb[b * U_ + i];
        sWv[i] = Wv[i];
    }
    __syncthreads();

    float acc[2][8][4];
    int gc = 0;

    for (int m = 0; m < NTILE; m++) {
        #pragma unroll
        for (int i = 0; i < 2; i++)
            #pragma unroll
            for (int j = 0; j < 8; j++)
                #pragma unroll
                for (int e = 0; e < 4; e++) acc[i][j][e] = 0.0f;

        for (int kc = 0; kc < 4; kc++, gc++) {
            CP_WAIT0();
            __syncthreads();             // chunk gc ready; all warps past buf (gc-1)
            if (gc + 1 < NCHUNK) issue(gc + 1);

            const float* Ath = sA + (gc & 1) * A_BUF_F + (wm * 32 + g) * ASTRIDE + q;
            const float* Bth = sB + kc * 64 * BSTRIDE + q * BSTRIDE + wn * 64 + g;

            #pragma unroll
            for (int k8 = 0; k8 < 8; k8++) {
                uint32_t a[2][4];
                #pragma unroll
                for (int i = 0; i < 2; i++) {
                    const float* ap = Ath + i * (16 * ASTRIDE) + k8 * 8;
                    a[i][0] = rna_tf32(ap[0]);
                    a[i][1] = rna_tf32(ap[8 * ASTRIDE]);
                    a[i][2] = rna_tf32(ap[4]);
                    a[i][3] = rna_tf32(ap[8 * ASTRIDE + 4]);
                }
                const float* bp = Bth + (k8 * 8) * BSTRIDE;
                #pragma unroll
                for (int j = 0; j < 8; j++) {
                    uint32_t b0 = __float_as_uint(bp[j * 8]);
                    uint32_t b1 = __float_as_uint(bp[4 * BSTRIDE + j * 8]);
                    mma_tf32(acc[0][j], a[0], b0, b1);
                    mma_tf32(acc[1][j], a[1], b0, b1);
                }
            }
        }

        // ---- epilogue: score[s] = sum_u tanh(acc+qpb[u])*Wv[u] + bv ----
        float p[4] = {0.f, 0.f, 0.f, 0.f};
        #pragma unroll
        for (int i = 0; i < 2; i++)
            #pragma unroll
            for (int j = 0; j < 8; j++) {
                int ub = wn * 64 + j * 8 + q * 2;
                float w0 = sWv[ub], w1 = sWv[ub + 1];
                float q0 = sQ[ub],  q1 = sQ[ub + 1];
                p[i * 2]     += tanh_fast(acc[i][j][0] + q0) * w0
                              + tanh_fast(acc[i][j][1] + q1) * w1;
                p[i * 2 + 1] += tanh_fast(acc[i][j][2] + q0) * w0
                              + tanh_fast(acc[i][j][3] + q1) * w1;
            }
        #pragma unroll
        for (int e = 0; e < 4; e++) {
            p[e] += __shfl_xor_sync(0xffffffffu, p[e], 1);
            p[e] += __shfl_xor_sync(0xffffffffu, p[e], 2);
        }
        if (q == 0) {
            float* sr = sred + wn * 128 + wm * 32 + g;
            sr[0]  = p[0];
            sr[8]  = p[1];
            sr[16] = p[2];
            sr[24] = p[3];
        }
        __syncthreads();
        if (tid < 128)
            g_score[(size_t)b * S_ + s0 + m * 128 + tid] =
                sred[tid] + sred[128 + tid] + bvv;
        // next sred write is >=4 __syncthreads away (chunk loop) — safe
    }
}

// ---------------------------------------------------------------------------
// K3: softmax over seq per batch -> attention weights (part of output)
// ---------------------------------------------------------------------------
__global__ __launch_bounds__(256)
void softmax_kernel(float* __restrict__ out_w) {
    int b = blockIdx.x;
    int tid = threadIdx.x;   // 256
    __shared__ float red[256];
    const float* sc = g_score + (size_t)b * S_;

    float v[16];
    float mx = -1e30f;
    #pragma unroll
    for (int k = 0; k < 16; k++) {
        v[k] = sc[tid + k * 256];
        mx = fmaxf(mx, v[k]);
    }
    red[tid] = mx;
    __syncthreads();
    for (int off = 128; off > 0; off >>= 1) {
        if (tid < off) red[tid] = fmaxf(red[tid], red[tid + off]);
        __syncthreads();
    }
    mx = red[0];
    __syncthreads();

    float sum = 0.0f;
    #pragma unroll
    for (int k = 0; k < 16; k++) {
        v[k] = expf(v[k] - mx);
        sum += v[k];
    }
    red[tid] = sum;
    __syncthreads();
    for (int off = 128; off > 0; off >>= 1) {
        if (tid < off) red[tid] += red[tid + off];
        __syncthreads();
    }
    float inv = 1.0f / red[0];

    float* w = out_w + (size_t)b * S_;
    #pragma unroll
    for (int k = 0; k < 16; k++)
        w[tid + k * 256] = v[k] * inv;
}

// ---------------------------------------------------------------------------
// K4a: context partials. Grid = B*CSPLIT blocks; each handles 512 seq rows.
// ---------------------------------------------------------------------------
__global__ __launch_bounds__(256)
void context_part_kernel(const float* __restrict__ values,
                         const float* __restrict__ weights) {
    int b  = blockIdx.x >> 3;
    int sp = blockIdx.x & 7;
    int tid = threadIdx.x;
    __shared__ float sw_[512];
    __shared__ float4 sr[256];
    for (int i = tid; i < 512; i += 256) sw_[i] = weights[(size_t)b * S_ + sp * 512 + i];
    __syncthreads();

    int f4 = tid & 63, st = tid >> 6;  // 64 float4 cols x 4 seq stripes
    const float4* vp = (const float4*)(values + ((size_t)b * S_ + sp * 512) * D_) + f4;
    float4 acc = make_float4(0.f, 0.f, 0.f, 0.f);
    #pragma unroll 8
    for (int s = st; s < 512; s += 4) {
        float wv = sw_[s];
        float4 v = vp[(size_t)s * 64];
        acc.x += wv * v.x; acc.y += wv * v.y; acc.z += wv * v.z; acc.w += wv * v.w;
    }
    sr[st * 64 + f4] = acc;
    __syncthreads();
    if (tid < 64) {
        float4 a = sr[tid], b1 = sr[64 + tid], c = sr[128 + tid], d = sr[192 + tid];
        a.x += b1.x + c.x + d.x;
        a.y += b1.y + c.y + d.y;
        a.z += b1.z + c.z + d.z;
        a.w += b1.w + c.w + d.w;
        ((float4*)(g_cpart + ((size_t)sp * B_ + b) * D_))[tid] = a;
    }
}

// K4b: reduce partials (deterministic)
__global__ void context_reduce_kernel(float* __restrict__ ctx) {
    int b = blockIdx.x;
    int d = threadIdx.x;  // 256
    float a = 0.f;
    #pragma unroll
    for (int sp = 0; sp < CSPLIT; sp++)
        a += g_cpart[((size_t)sp * B_ + b) * D_ + d];
    ctx[b * D_ + d] = a;
}

// ---------------------------------------------------------------------------
extern "C" void kernel_launch(void* const* d_in, const int* in_sizes, int n_in,
                              void* d_out, int out_size) {
    const float* query  = (const float*)d_in[0];
    const float* values = (const float*)d_in[1];
    const float* W1     = (const float*)d_in[2];
    const float* b1     = (const float*)d_in[3];
    const float* W2     = (const float*)d_in[4];
    const float* b2     = (const float*)d_in[5];
    const float* Wv     = (const float*)d_in[6];
    const float* bv     = (const float*)d_in[7];

    float* out  = (float*)d_out;
    float* ctx  = out;             // [B, D]
    float* wout = out + B_ * D_;   // [B, S, 1]

    cudaFuncSetAttribute(score_mma_kernel,
                         cudaFuncAttributeMaxDynamicSharedMemorySize, SMEM_SC);

    qproj_kernel<<<B_, U_>>>(query, W1, b1, b2);
    score_mma_kernel<<<B_ * 8, 256, SMEM_SC>>>(values, W2, Wv, bv);
    softmax_kernel<<<B_, 256>>>(wout);
    context_part_kernel<<<B_ * CSPLIT, 256>>>(values, wout);
    context_reduce_kernel<<<B_, 256>>>(ctx);
}

// round 5
// speedup vs baseline: 3.2910x; 1.0885x over previous
#include <cuda_runtime.h>
#include <cstdint>
#include <math.h>

#define B_ 128
#define S_ 4096
#define D_ 256
#define U_ 128

// ---------------- device scratch (no allocs allowed) ----------------
__device__ float g_qpb[B_ * U_];                 // q@W1 + b1 + b2
__device__ float g_score[B_ * S_];               // pre-softmax scores
#define CSPLIT 8
__device__ float g_cpart[CSPLIT * B_ * D_];      // context partials

// ---------------- helpers ----------------
__device__ __forceinline__ uint32_t smem_u32(const void* p) {
    uint32_t a;
    asm("{ .reg .u64 t; cvta.to.shared.u64 t, %1; cvt.u32.u64 %0, t; }" : "=r"(a) : "l"(p));
    return a;
}
__device__ __forceinline__ void cp_async16(uint32_t dst, const void* src) {
    asm volatile("cp.async.cg.shared.global [%0], [%1], 16;" :: "r"(dst), "l"(src));
}
#define CP_COMMIT() asm volatile("cp.async.commit_group;" ::: "memory")
#define CP_WAIT0()  asm volatile("cp.async.wait_group 0;" ::: "memory")

__device__ __forceinline__ uint32_t rna_tf32(float f) {
    uint32_t r;
    asm("cvt.rna.tf32.f32 %0, %1;" : "=r"(r) : "f"(f));
    return r;
}

// mma.sync m16n8k8 tf32: D += A*B  (row.col). HW truncates operand mantissas,
// so raw fp32 bits in A are accepted (RZ behavior); B is RNA-rounded at stage.
__device__ __forceinline__ void mma_tf32(float* d, const uint32_t* a,
                                         uint32_t b0, uint32_t b1) {
    asm volatile(
        "mma.sync.aligned.m16n8k8.row.col.f32.tf32.tf32.f32 "
        "{%0,%1,%2,%3}, {%4,%5,%6,%7}, {%8,%9}, {%0,%1,%2,%3};"
        : "+f"(d[0]), "+f"(d[1]), "+f"(d[2]), "+f"(d[3])
        : "r"(a[0]), "r"(a[1]), "r"(a[2]), "r"(a[3]), "r"(b0), "r"(b1));
}

__device__ __forceinline__ float tanh_fast(float x) {
    float ax = fabsf(x);
    float e  = __expf(ax + ax);
    float t  = 1.0f - __fdividef(2.0f, e + 1.0f);
    return copysignf(t, x);
}

// ---------------------------------------------------------------------------
// K1: qpb[b,u] = query[b,:]@W1[:,u] + b1[u] + b2[u]
// ---------------------------------------------------------------------------
__global__ void qproj_kernel(const float* __restrict__ query,
                             const float* __restrict__ W1,
                             const float* __restrict__ b1,
                             const float* __restrict__ b2) {
    int b = blockIdx.x;
    int u = threadIdx.x;
    __shared__ float sq[D_];
    for (int i = threadIdx.x; i < D_; i += blockDim.x) sq[i] = query[b * D_ + i];
    __syncthreads();
    float acc = b1[u] + b2[u];
    #pragma unroll 8
    for (int d = 0; d < D_; d++) acc += sq[d] * W1[d * U_ + u];
    g_qpb[b * U_ + u] = acc;
}

// ---------------------------------------------------------------------------
// K2: score kernel via mma.sync tf32 (HMMA path).
//   Grid = 1024 CTAs: b = bid>>3, s0 = (bid&7)*512. Each CTA: 4 tiles of 128 seq.
//   512 threads = 16 warps, warp grid 4(M)x4(N), warp tile 32 seq x 32 units.
//   K=256 staged as 4 chunks of 64, double-buffered cp.async.
//   SMEM floats: sQ[128] | sWv[128] | sred[512] | A 2x(128x68) | B 256x136
// ---------------------------------------------------------------------------
#define ASTRIDE 68
#define BSTRIDE 136
#define A_BUF_F (128 * ASTRIDE)                 // 8704 floats per buffer
#define OFF_A_F 768
#define OFF_B_F (OFF_A_F + 2 * A_BUF_F)         // 18176
#define SMEM_F  (OFF_B_F + D_ * BSTRIDE)        // 52992 floats
#define SMEM_SC (SMEM_F * 4)                    // 211968 bytes

#define NTILE  4
#define NCHUNK 16   // NTILE * 4

__global__ __launch_bounds__(512, 1)
void score_mma_kernel(const float* __restrict__ values,
                      const float* __restrict__ W2,
                      const float* __restrict__ Wv,
                      const float* __restrict__ bv) {
    extern __shared__ float sm[];
    float* sQ   = sm;
    float* sWv  = sm + 128;
    float* sred = sm + 256;          // 512 floats
    float* sA   = sm + OFF_A_F;
    float* sB   = sm + OFF_B_F;

    const int tid  = threadIdx.x;
    const int wid  = tid >> 5;
    const int lane = tid & 31;
    const int g    = lane >> 2;     // row within frag
    const int q    = lane & 3;      // col group within frag
    const int wm   = wid >> 2;      // warp M index (0..3)
    const int wn   = wid & 3;       // warp N index (0..3)

    const int b  = blockIdx.x >> 3;
    const int s0 = (blockIdx.x & 7) * 512;
    const float bvv = bv[0];

    // ---- prologue: start first A chunk immediately ----
    auto issue = [&](int gc) {
        int mm = gc >> 2, kc = gc & 3;
        const float* src = values + ((size_t)(b * S_ + s0 + mm * 128)) * D_ + kc * 64;
        float* dst = sA + (gc & 1) * A_BUF_F;
        #pragma unroll
        for (int kk = 0; kk < 4; kk++) {
            int idx = tid + kk * 512;
            int row = idx >> 4, f4 = idx & 15;
            cp_async16(smem_u32(dst + row * ASTRIDE + f4 * 4),
                       src + (size_t)row * D_ + f4 * 4);
        }
        CP_COMMIT();
    };
    issue(0);

    // ---- stage B = W2 [k][u] tf32-RNA-rounded, padded stride 136 ----
    for (int idx = tid; idx < D_ * U_; idx += 512) {
        int k = idx >> 7, u = idx & 127;
        sB[k * BSTRIDE + u] = __uint_as_float(rna_tf32(W2[idx]));
    }
    for (int i = tid; i < U_; i += 512) {
        sQ[i]  = g_qpb[b * U_ + i];
        sWv[i] = Wv[i];
    }
    __syncthreads();

    float acc[2][4][4];
    int gc = 0;

    for (int m = 0; m < NTILE; m++) {
        #pragma unroll
        for (int i = 0; i < 2; i++)
            #pragma unroll
            for (int j = 0; j < 4; j++)
                #pragma unroll
                for (int e = 0; e < 4; e++) acc[i][j][e] = 0.0f;

        for (int kc = 0; kc < 4; kc++, gc++) {
            CP_WAIT0();
            __syncthreads();             // chunk gc ready; all warps past buf (gc-1)
            if (gc + 1 < NCHUNK) issue(gc + 1);

            const float* Ath = sA + (gc & 1) * A_BUF_F + (wm * 32 + g) * ASTRIDE + q;
            const float* Bth = sB + kc * 64 * BSTRIDE + q * BSTRIDE + wn * 32 + g;

            #pragma unroll
            for (int k8 = 0; k8 < 8; k8++) {
                uint32_t a[2][4];
                #pragma unroll
                for (int i = 0; i < 2; i++) {
                    const float* ap = Ath + i * (16 * ASTRIDE) + k8 * 8;
                    a[i][0] = __float_as_uint(ap[0]);
                    a[i][1] = __float_as_uint(ap[8 * ASTRIDE]);
                    a[i][2] = __float_as_uint(ap[4]);
                    a[i][3] = __float_as_uint(ap[8 * ASTRIDE + 4]);
                }
                const float* bp = Bth + (k8 * 8) * BSTRIDE;
                #pragma unroll
                for (int j = 0; j < 4; j++) {
                    uint32_t b0 = __float_as_uint(bp[j * 8]);
                    uint32_t b1 = __float_as_uint(bp[4 * BSTRIDE + j * 8]);
                    mma_tf32(acc[0][j], a[0], b0, b1);
                    mma_tf32(acc[1][j], a[1], b0, b1);
                }
            }
        }

        // ---- epilogue: score[s] = sum_u tanh(acc+qpb[u])*Wv[u] + bv ----
        float p[4] = {0.f, 0.f, 0.f, 0.f};
        #pragma unroll
        for (int i = 0; i < 2; i++)
            #pragma unroll
            for (int j = 0; j < 4; j++) {
                int ub = wn * 32 + j * 8 + q * 2;
                float w0 = sWv[ub], w1 = sWv[ub + 1];
                float q0 = sQ[ub],  q1 = sQ[ub + 1];
                p[i * 2]     += tanh_fast(acc[i][j][0] + q0) * w0
                              + tanh_fast(acc[i][j][1] + q1) * w1;
                p[i * 2 + 1] += tanh_fast(acc[i][j][2] + q0) * w0
                              + tanh_fast(acc[i][j][3] + q1) * w1;
            }
        #pragma unroll
        for (int e = 0; e < 4; e++) {
            p[e] += __shfl_xor_sync(0xffffffffu, p[e], 1);
            p[e] += __shfl_xor_sync(0xffffffffu, p[e], 2);
        }
        if (q == 0) {
            float* sr = sred + wn * 128 + wm * 32 + g;
            sr[0]  = p[0];   // row wm*32+g      (i=0, D rows g)
            sr[8]  = p[1];   // row wm*32+g+8    (i=0, D rows g+8)
            sr[16] = p[2];   // row wm*32+g+16   (i=1)
            sr[24] = p[3];   // row wm*32+g+24   (i=1)
        }
        __syncthreads();
        if (tid < 128)
            g_score[(size_t)b * S_ + s0 + m * 128 + tid] =
                sred[tid] + sred[128 + tid] + sred[256 + tid] + sred[384 + tid] + bvv;
        // next sred write is >=1 __syncthreads away (chunk loop) — safe
    }
}

// ---------------------------------------------------------------------------
// K3: softmax over seq per batch -> attention weights (part of output)
// ---------------------------------------------------------------------------
__global__ __launch_bounds__(512)
void softmax_kernel(float* __restrict__ out_w) {
    int b = blockIdx.x;
    int tid = threadIdx.x;   // 512
    __shared__ float red[512];
    const float* sc = g_score + (size_t)b * S_;

    float v[8];
    float mx = -1e30f;
    #pragma unroll
    for (int k = 0; k < 8; k++) {
        v[k] = sc[tid + k * 512];
        mx = fmaxf(mx, v[k]);
    }
    red[tid] = mx;
    __syncthreads();
    for (int off = 256; off > 0; off >>= 1) {
        if (tid < off) red[tid] = fmaxf(red[tid], red[tid + off]);
        __syncthreads();
    }
    mx = red[0];
    __syncthreads();

    float sum = 0.0f;
    #pragma unroll
    for (int k = 0; k < 8; k++) {
        v[k] = expf(v[k] - mx);
        sum += v[k];
    }
    red[tid] = sum;
    __syncthreads();
    for (int off = 256; off > 0; off >>= 1) {
        if (tid < off) red[tid] += red[tid + off];
        __syncthreads();
    }
    float inv = 1.0f / red[0];

    float* w = out_w + (size_t)b * S_;
    #pragma unroll
    for (int k = 0; k < 8; k++)
        w[tid + k * 512] = v[k] * inv;
}

// ---------------------------------------------------------------------------
// K4a: context partials. Grid = B*CSPLIT blocks; each handles 512 seq rows.
// ---------------------------------------------------------------------------
__global__ __launch_bounds__(256)
void context_part_kernel(const float* __restrict__ values,
                         const float* __restrict__ weights) {
    int b  = blockIdx.x >> 3;
    int sp = blockIdx.x & 7;
    int tid = threadIdx.x;
    __shared__ float sw_[512];
    __shared__ float4 sr[256];
    for (int i = tid; i < 512; i += 256) sw_[i] = weights[(size_t)b * S_ + sp * 512 + i];
    __syncthreads();

    int f4 = tid & 63, st = tid >> 6;  // 64 float4 cols x 4 seq stripes
    const float4* vp = (const float4*)(values + ((size_t)b * S_ + sp * 512) * D_) + f4;
    float4 acc = make_float4(0.f, 0.f, 0.f, 0.f);
    #pragma unroll 8
    for (int s = st; s < 512; s += 4) {
        float wv = sw_[s];
        float4 v = vp[(size_t)s * 64];
        acc.x += wv * v.x; acc.y += wv * v.y; acc.z += wv * v.z; acc.w += wv * v.w;
    }
    sr[st * 64 + f4] = acc;
    __syncthreads();
    if (tid < 64) {
        float4 a = sr[tid], b1 = sr[64 + tid], c = sr[128 + tid], d = sr[192 + tid];
        a.x += b1.x + c.x + d.x;
        a.y += b1.y + c.y + d.y;
        a.z += b1.z + c.z + d.z;
        a.w += b1.w + c.w + d.w;
        ((float4*)(g_cpart + ((size_t)sp * B_ + b) * D_))[tid] = a;
    }
}

// K4b: reduce partials (deterministic)
__global__ void context_reduce_kernel(float* __restrict__ ctx) {
    int b = blockIdx.x;
    int d = threadIdx.x;  // 256
    float a = 0.f;
    #pragma unroll
    for (int sp = 0; sp < CSPLIT; sp++)
        a += g_cpart[((size_t)sp * B_ + b) * D_ + d];
    ctx[b * D_ + d] = a;
}

// ---------------------------------------------------------------------------
extern "C" void kernel_launch(void* const* d_in, const int* in_sizes, int n_in,
                              void* d_out, int out_size) {
    const float* query  = (const float*)d_in[0];
    const float* values = (const float*)d_in[1];
    const float* W1     = (const float*)d_in[2];
    const float* b1     = (const float*)d_in[3];
    const float* W2     = (const float*)d_in[4];
    const float* b2     = (const float*)d_in[5];
    const float* Wv     = (const float*)d_in[6];
    const float* bv     = (const float*)d_in[7];

    float* out  = (float*)d_out;
    float* ctx  = out;             // [B, D]
    float* wout = out + B_ * D_;   // [B, S, 1]

    cudaFuncSetAttribute(score_mma_kernel,
                         cudaFuncAttributeMaxDynamicSharedMemorySize, SMEM_SC);

    qproj_kernel<<<B_, U_>>>(query, W1, b1, b2);
    score_mma_kernel<<<B_ * 8, 512, SMEM_SC>>>(values, W2, Wv, bv);
    softmax_kernel<<<B_, 512>>>(wout);
    context_part_kernel<<<B_ * CSPLIT, 256>>>(values, wout);
    context_reduce_kernel<<<B_, 256>>>(ctx);
}

// round 6
// speedup vs baseline: 3.5803x; 1.0879x over previous
#include <cuda_runtime.h>
#include <cstdint>
#include <math.h>

#define B_ 128
#define S_ 4096
#define D_ 256
#define U_ 128

// ---------------- device scratch (no allocs allowed) ----------------
__device__ float g_qpb[B_ * U_];                 // q@W1 + b1 + b2
__device__ float g_score[B_ * S_];               // pre-softmax scores
#define CSPLIT 8
__device__ float g_cpart[CSPLIT * B_ * D_];      // context partials

// ---------------- helpers ----------------
__device__ __forceinline__ uint32_t smem_u32(const void* p) {
    uint32_t a;
    asm("{ .reg .u64 t; cvta.to.shared.u64 t, %1; cvt.u32.u64 %0, t; }" : "=r"(a) : "l"(p));
    return a;
}
__device__ __forceinline__ void cp_async16(uint32_t dst, const void* src) {
    asm volatile("cp.async.cg.shared.global [%0], [%1], 16;" :: "r"(dst), "l"(src));
}
#define CP_COMMIT() asm volatile("cp.async.commit_group;" ::: "memory")
#define CP_WAIT0()  asm volatile("cp.async.wait_group 0;" ::: "memory")

__device__ __forceinline__ uint32_t rna_tf32(float f) {
    uint32_t r;
    asm("cvt.rna.tf32.f32 %0, %1;" : "=r"(r) : "f"(f));
    return r;
}

// ldmatrix x4 (b16 reinterpret carries tf32 words: each 32-bit chunk = 1 tf32)
#define LDSM4(r, addr) \
    asm volatile("ldmatrix.sync.aligned.m8n8.x4.shared.b16 {%0,%1,%2,%3}, [%4];" \
        : "=r"((r)[0]), "=r"((r)[1]), "=r"((r)[2]), "=r"((r)[3]) : "r"(addr))

// mma.sync m16n8k8 tf32: D += A*B (row.col). Raw fp32 bits in A (HW truncates);
// B RNA-rounded at stage time.
__device__ __forceinline__ void mma_tf32(float* d, const uint32_t* a,
                                         uint32_t b0, uint32_t b1) {
    asm volatile(
        "mma.sync.aligned.m16n8k8.row.col.f32.tf32.tf32.f32 "
        "{%0,%1,%2,%3}, {%4,%5,%6,%7}, {%8,%9}, {%0,%1,%2,%3};"
        : "+f"(d[0]), "+f"(d[1]), "+f"(d[2]), "+f"(d[3])
        : "r"(a[0]), "r"(a[1]), "r"(a[2]), "r"(a[3]), "r"(b0), "r"(b1));
}

__device__ __forceinline__ float tanh_fast(float x) {
    float ax = fabsf(x);
    float e  = __expf(ax + ax);
    float t  = 1.0f - __fdividef(2.0f, e + 1.0f);
    return copysignf(t, x);
}

// ---------------------------------------------------------------------------
// K1: qpb[b,u] = query[b,:]@W1[:,u] + b1[u] + b2[u]
// ---------------------------------------------------------------------------
__global__ void qproj_kernel(const float* __restrict__ query,
                             const float* __restrict__ W1,
                             const float* __restrict__ b1,
                             const float* __restrict__ b2) {
    int b = blockIdx.x;
    int u = threadIdx.x;
    __shared__ float sq[D_];
    for (int i = threadIdx.x; i < D_; i += blockDim.x) sq[i] = query[b * D_ + i];
    __syncthreads();
    float acc = b1[u] + b2[u];
    #pragma unroll 8
    for (int d = 0; d < D_; d++) acc += sq[d] * W1[d * U_ + u];
    g_qpb[b * U_ + u] = acc;
}

// ---------------------------------------------------------------------------
// K2: score kernel, mma.sync tf32 + ldmatrix.
//   Grid = 512 CTAs: b = bid>>2, s0 = (bid&3)*1024. Each CTA: 4 tiles of 256 seq.
//   512 threads = 16 warps, warp grid 4(M)x4(N), warp tile 64 seq x 32 units.
//   K=256 staged per tile as 8 chunks of 32, double-buffered cp.async.
//   A smem: [256 rows][36 pad] x2 (144B row stride -> conflict-free ldmatrix).
//   B smem: W2^T [128 u][260 pad] (1040B stride -> conflict-free ldmatrix).
// ---------------------------------------------------------------------------
#define ASTR    36
#define ASTR_B  144
#define BSTR    260
#define BSTR_B  1040
#define ABUF_F  (256 * ASTR)                    // 9216 floats per buffer
#define OFF_A_F 1280                            // sQ 128 | sWv 128 | sred 1024
#define OFF_B_F (OFF_A_F + 2 * ABUF_F)          // 19712
#define SMEM_F  (OFF_B_F + U_ * BSTR)           // 52992 floats
#define SMEM_SC (SMEM_F * 4)                    // 211968 bytes

#define NTILE   4
#define KCHUNKS 8    // per tile, k=32 each
#define NCHUNK  (NTILE * KCHUNKS)   // 32

__global__ __launch_bounds__(512, 1)
void score_mma_kernel(const float* __restrict__ values,
                      const float* __restrict__ W2,
                      const float* __restrict__ Wv,
                      const float* __restrict__ bv) {
    extern __shared__ float sm[];
    float* sQ   = sm;
    float* sWv  = sm + 128;
    float* sred = sm + 256;          // 1024 floats
    float* sA   = sm + OFF_A_F;
    float* sBT  = sm + OFF_B_F;

    const int tid  = threadIdx.x;
    const int wid  = tid >> 5;
    const int lane = tid & 31;
    const int g    = lane >> 2;
    const int q    = lane & 3;
    const int wm   = wid >> 2;      // warp M (0..3): 64 seq rows each
    const int wn   = wid & 3;       // warp N (0..3): 32 units each

    const int b  = blockIdx.x >> 2;
    const int s0 = (blockIdx.x & 3) * 1024;
    const float bvv = bv[0];

    const uint32_t smA_b  = smem_u32(sA);
    const uint32_t smBT_b = smem_u32(sBT);

    // ---- prologue: start first A chunk immediately ----
    auto issue = [&](int gc) {
        int mm = gc >> 3, kc = gc & 7;
        const float* src = values + ((size_t)(b * S_ + s0 + mm * 256)) * D_ + kc * 32;
        uint32_t dstb = smA_b + (gc & 1) * (ABUF_F * 4);
        #pragma unroll
        for (int it = 0; it < 4; it++) {
            int idx = tid + it * 512;        // 2048 granules: 256 rows x 8 float4
            int row = idx >> 3, f4 = idx & 7;
            cp_async16(dstb + row * ASTR_B + f4 * 16,
                       src + (size_t)row * D_ + f4 * 4);
        }
        CP_COMMIT();
    };
    issue(0);

    // ---- stage B = W2^T [u][k], tf32-RNA-rounded ----
    for (int idx = tid; idx < D_ * U_; idx += 512) {
        int k = idx >> 7, u = idx & 127;
        sBT[u * BSTR + k] = __uint_as_float(rna_tf32(W2[idx]));
    }
    for (int i = tid; i < U_; i += 512) {
        sQ[i]  = g_qpb[b * U_ + i];
        sWv[i] = Wv[i];
    }
    __syncthreads();

    // ---- ldmatrix per-thread address components ----
    // A frag (m16n8k8): m0 rows 0-7 k0-3 | m1 rows 8-15 k0-3 | m2 rows 0-7 k4-7 | m3 rows 8-15 k4-7
    const int a_row  = wm * 64 + ((lane < 16) ? lane : (lane - 16));
    const int a_koff = (lane < 16) ? 0 : 4;
    uint32_t aoff[4];
    #pragma unroll
    for (int i = 0; i < 4; i++)
        aoff[i] = (uint32_t)((a_row + i * 16) * ASTR_B + a_koff * 4);
    // B frag from BT[u][k]: m0 n(j even) k0-3 | m1 n(j even) k4-7 | m2 n(j odd) k0-3 | m3 n(j odd) k4-7
    const int b_row  = wn * 32 + (lane & 7) + ((lane >= 16) ? 8 : 0);
    const int b_koff = ((lane >> 3) & 1) * 4;
    uint32_t boff[2];
    #pragma unroll
    for (int j2 = 0; j2 < 2; j2++)
        boff[j2] = smBT_b + (uint32_t)((b_row + j2 * 16) * BSTR_B + b_koff * 4);

    float acc[4][4][4];
    int gc = 0;

    for (int m = 0; m < NTILE; m++) {
        #pragma unroll
        for (int i = 0; i < 4; i++)
            #pragma unroll
            for (int j = 0; j < 4; j++)
                #pragma unroll
                for (int e = 0; e < 4; e++) acc[i][j][e] = 0.0f;

        for (int kc = 0; kc < KCHUNKS; kc++, gc++) {
            CP_WAIT0();
            __syncthreads();             // chunk gc ready; all warps past buf (gc-1)
            if (gc + 1 < NCHUNK) issue(gc + 1);

            uint32_t aB = smA_b + (gc & 1) * (ABUF_F * 4);
            uint32_t bK = (uint32_t)(kc * 128);   // kc*32 floats = kc*128 bytes

            #pragma unroll
            for (int k8 = 0; k8 < 4; k8++) {
                uint32_t a[4][4];
                #pragma unroll
                for (int i = 0; i < 4; i++)
                    LDSM4(a[i], aB + aoff[i] + k8 * 32);
                uint32_t bf[2][4];
                LDSM4(bf[0], boff[0] + bK + k8 * 32);
                LDSM4(bf[1], boff[1] + bK + k8 * 32);
                #pragma unroll
                for (int j2 = 0; j2 < 2; j2++)
                    #pragma unroll
                    for (int jj = 0; jj < 2; jj++) {
                        int j = j2 * 2 + jj;
                        uint32_t b0 = bf[j2][jj * 2], b1 = bf[j2][jj * 2 + 1];
                        #pragma unroll
                        for (int i = 0; i < 4; i++)
                            mma_tf32(acc[i][j], a[i], b0, b1);
                    }
            }
        }

        // ---- epilogue: score[s] = sum_u tanh(vproj+qpb[u])*Wv[u] + bv ----
        float p[8];
        #pragma unroll
        for (int e = 0; e < 8; e++) p[e] = 0.0f;
        #pragma unroll
        for (int i = 0; i < 4; i++)
            #pragma unroll
            for (int j = 0; j < 4; j++) {
                int ub = wn * 32 + j * 8 + q * 2;
                float w0 = sWv[ub], w1 = sWv[ub + 1];
                float q0 = sQ[ub],  q1 = sQ[ub + 1];
                p[i * 2]     += tanh_fast(acc[i][j][0] + q0) * w0
                              + tanh_fast(acc[i][j][1] + q1) * w1;
                p[i * 2 + 1] += tanh_fast(acc[i][j][2] + q0) * w0
                              + tanh_fast(acc[i][j][3] + q1) * w1;
            }
        #pragma unroll
        for (int e = 0; e < 8; e++) {
            p[e] += __shfl_xor_sync(0xffffffffu, p[e], 1);
            p[e] += __shfl_xor_sync(0xffffffffu, p[e], 2);
        }
        if (q == 0) {
            float* sr = sred + wn * 256 + wm * 64;
            #pragma unroll
            for (int i = 0; i < 4; i++) {
                sr[i * 16 + g]     = p[i * 2];
                sr[i * 16 + g + 8] = p[i * 2 + 1];
            }
        }
        __syncthreads();
        if (tid < 256)
            g_score[(size_t)b * S_ + s0 + m * 256 + tid] =
                sred[tid] + sred[256 + tid] + sred[512 + tid] + sred[768 + tid] + bvv;
        // next sred write is gated by the chunk-loop CP_WAIT0+__syncthreads — safe
    }
}

// ---------------------------------------------------------------------------
// K3: softmax over seq per batch -> attention weights (part of output)
// ---------------------------------------------------------------------------
__global__ __launch_bounds__(512)
void softmax_kernel(float* __restrict__ out_w) {
    int b = blockIdx.x;
    int tid = threadIdx.x;   // 512
    __shared__ float red[512];
    const float* sc = g_score + (size_t)b * S_;

    float v[8];
    float mx = -1e30f;
    #pragma unroll
    for (int k = 0; k < 8; k++) {
        v[k] = sc[tid + k * 512];
        mx = fmaxf(mx, v[k]);
    }
    red[tid] = mx;
    __syncthreads();
    for (int off = 256; off > 0; off >>= 1) {
        if (tid < off) red[tid] = fmaxf(red[tid], red[tid + off]);
        __syncthreads();
    }
    mx = red[0];
    __syncthreads();

    float sum = 0.0f;
    #pragma unroll
    for (int k = 0; k < 8; k++) {
        v[k] = expf(v[k] - mx);
        sum += v[k];
    }
    red[tid] = sum;
    __syncthreads();
    for (int off = 256; off > 0; off >>= 1) {
        if (tid < off) red[tid] += red[tid + off];
        __syncthreads();
    }
    float inv = 1.0f / red[0];

    float* w = out_w + (size_t)b * S_;
    #pragma unroll
    for (int k = 0; k < 8; k++)
        w[tid + k * 512] = v[k] * inv;
}

// ---------------------------------------------------------------------------
// K4a: context partials. Grid = B*CSPLIT blocks; each handles 512 seq rows.
// ---------------------------------------------------------------------------
__global__ __launch_bounds__(256)
void context_part_kernel(const float* __restrict__ values,
                         const float* __restrict__ weights) {
    int b  = blockIdx.x >> 3;
    int sp = blockIdx.x & 7;
    int tid = threadIdx.x;
    __shared__ float sw_[512];
    __shared__ float4 sr[256];
    for (int i = tid; i < 512; i += 256) sw_[i] = weights[(size_t)b * S_ + sp * 512 + i];
    __syncthreads();

    int f4 = tid & 63, st = tid >> 6;  // 64 float4 cols x 4 seq stripes
    const float4* vp = (const float4*)(values + ((size_t)b * S_ + sp * 512) * D_) + f4;
    float4 acc = make_float4(0.f, 0.f, 0.f, 0.f);
    #pragma unroll 8
    for (int s = st; s < 512; s += 4) {
        float wv = sw_[s];
        float4 v = vp[(size_t)s * 64];
        acc.x += wv * v.x; acc.y += wv * v.y; acc.z += wv * v.z; acc.w += wv * v.w;
    }
    sr[st * 64 + f4] = acc;
    __syncthreads();
    if (tid < 64) {
        float4 a = sr[tid], b1 = sr[64 + tid], c = sr[128 + tid], d = sr[192 + tid];
        a.x += b1.x + c.x + d.x;
        a.y += b1.y + c.y + d.y;
        a.z += b1.z + c.z + d.z;
        a.w += b1.w + c.w + d.w;
        ((float4*)(g_cpart + ((size_t)sp * B_ + b) * D_))[tid] = a;
    }
}

// K4b: reduce partials (deterministic)
__global__ void context_reduce_kernel(float* __restrict__ ctx) {
    int b = blockIdx.x;
    int d = threadIdx.x;  // 256
    float a = 0.f;
    #pragma unroll
    for (int sp = 0; sp < CSPLIT; sp++)
        a += g_cpart[((size_t)sp * B_ + b) * D_ + d];
    ctx[b * D_ + d] = a;
}

// ---------------------------------------------------------------------------
extern "C" void kernel_launch(void* const* d_in, const int* in_sizes, int n_in,
                              void* d_out, int out_size) {
    const float* query  = (const float*)d_in[0];
    const float* values = (const float*)d_in[1];
    const float* W1     = (const float*)d_in[2];
    const float* b1     = (const float*)d_in[3];
    const float* W2     = (const float*)d_in[4];
    const float* b2     = (const float*)d_in[5];
    const float* Wv     = (const float*)d_in[6];
    const float* bv     = (const float*)d_in[7];

    float* out  = (float*)d_out;
    float* ctx  = out;             // [B, D]
    float* wout = out + B_ * D_;   // [B, S, 1]

    cudaFuncSetAttribute(score_mma_kernel,
                         cudaFuncAttributeMaxDynamicSharedMemorySize, SMEM_SC);

    qproj_kernel<<<B_, U_>>>(query, W1, b1, b2);
    score_mma_kernel<<<B_ * 4, 512, SMEM_SC>>>(values, W2, Wv, bv);
    softmax_kernel<<<B_, 512>>>(wout);
    context_part_kernel<<<B_ * CSPLIT, 256>>>(values, wout);
    context_reduce_kernel<<<B_, 256>>>(ctx);
}

// round 7
// speedup vs baseline: 4.0815x; 1.1400x over previous
#include <cuda_runtime.h>
#include <cstdint>
#include <math.h>

#define B_ 128
#define S_ 4096
#define D_ 256
#define U_ 128

// ---------------- device scratch (no allocs allowed) ----------------
__device__ float g_qpb[B_ * U_];                 // q@W1 + b1 + b2
__device__ float g_score[B_ * S_];               // pre-softmax scores
__device__ float g_ctxp[4 * B_ * D_];            // flash context partials (4 seq-splits)
__device__ float g_mp[4 * B_];                   // per-split running max
__device__ float g_MZ[2 * B_];                   // global [m | Z] per batch

// ---------------- helpers ----------------
__device__ __forceinline__ uint32_t smem_u32(const void* p) {
    uint32_t a;
    asm("{ .reg .u64 t; cvta.to.shared.u64 t, %1; cvt.u32.u64 %0, t; }" : "=r"(a) : "l"(p));
    return a;
}
__device__ __forceinline__ void cp_async16(uint32_t dst, const void* src) {
    asm volatile("cp.async.cg.shared.global [%0], [%1], 16;" :: "r"(dst), "l"(src));
}
#define CP_COMMIT() asm volatile("cp.async.commit_group;" ::: "memory")
#define CP_WAIT0()  asm volatile("cp.async.wait_group 0;" ::: "memory")

__device__ __forceinline__ uint32_t rna_tf32(float f) {
    uint32_t r;
    asm("cvt.rna.tf32.f32 %0, %1;" : "=r"(r) : "f"(f));
    return r;
}

// ldmatrix x4 (b16 reinterpret carries tf32 words: each 32-bit chunk = 1 tf32)
#define LDSM4(r, addr) \
    asm volatile("ldmatrix.sync.aligned.m8n8.x4.shared.b16 {%0,%1,%2,%3}, [%4];" \
        : "=r"((r)[0]), "=r"((r)[1]), "=r"((r)[2]), "=r"((r)[3]) : "r"(addr))

// mma.sync m16n8k8 tf32: D += A*B (row.col)
__device__ __forceinline__ void mma_tf32(float* d, const uint32_t* a,
                                         uint32_t b0, uint32_t b1) {
    asm volatile(
        "mma.sync.aligned.m16n8k8.row.col.f32.tf32.tf32.f32 "
        "{%0,%1,%2,%3}, {%4,%5,%6,%7}, {%8,%9}, {%0,%1,%2,%3};"
        : "+f"(d[0]), "+f"(d[1]), "+f"(d[2]), "+f"(d[3])
        : "r"(a[0]), "r"(a[1]), "r"(a[2]), "r"(a[3]), "r"(b0), "r"(b1));
}

__device__ __forceinline__ float tanh_fast(float x) {
    float ax = fabsf(x);
    float e  = __expf(ax + ax);
    float t  = 1.0f - __fdividef(2.0f, e + 1.0f);
    return copysignf(t, x);
}

// ---------------------------------------------------------------------------
// K1: qpb[b,u] = query[b,:]@W1[:,u] + b1[u] + b2[u]
// ---------------------------------------------------------------------------
__global__ void qproj_kernel(const float* __restrict__ query,
                             const float* __restrict__ W1,
                             const float* __restrict__ b1,
                             const float* __restrict__ b2) {
    int b = blockIdx.x;
    int u = threadIdx.x;
    __shared__ float sq[D_];
    for (int i = threadIdx.x; i < D_; i += blockDim.x) sq[i] = query[b * D_ + i];
    __syncthreads();
    float acc = b1[u] + b2[u];
    #pragma unroll 8
    for (int d = 0; d < D_; d++) acc += sq[d] * W1[d * U_ + u];
    g_qpb[b * U_ + u] = acc;
}

// ---------------------------------------------------------------------------
// K2: FUSED score + flash-context kernel (mma.sync tf32 + ldmatrix).
//   Grid = 512 CTAs: b = bid>>2, s0 = (bid&3)*1024. Each CTA: 4 tiles of 256 seq.
//   512 threads = 16 warps, 4(M)x4(N), warp tile 64x32.
//   After each tile's scores: running-max flash accumulation of
//   exp(score-m)*values (values re-read via LDG, L2-hot from cp.async).
// ---------------------------------------------------------------------------
#define ASTR    36
#define ASTR_B  144
#define BSTR    260
#define BSTR_B  1040
#define ABUF_F  (256 * ASTR)                    // 9216 floats per buffer
// floats: sQ 128 | sWv 128 | sred 1024 | sE 256 | sM 16(pad)
#define OFF_E_F 1280
#define OFF_M_F 1536
#define OFF_A_F 1568
#define OFF_B_F (OFF_A_F + 2 * ABUF_F)          // 20000
#define SMEM_F  (OFF_B_F + U_ * BSTR)           // 53280 floats
#define SMEM_SC (SMEM_F * 4)                    // 213120 bytes

#define NTILE   4
#define KCHUNKS 8
#define NCHUNK  (NTILE * KCHUNKS)   // 32

__global__ __launch_bounds__(512, 1)
void score_mma_kernel(const float* __restrict__ values,
                      const float* __restrict__ W2,
                      const float* __restrict__ Wv,
                      const float* __restrict__ bv) {
    extern __shared__ float sm[];
    float* sQ   = sm;
    float* sWv  = sm + 128;
    float* sred = sm + 256;          // 1024 floats
    float* sE   = sm + OFF_E_F;      // 256 floats
    float* sM   = sm + OFF_M_F;      // running max
    float* sA   = sm + OFF_A_F;
    float* sBT  = sm + OFF_B_F;

    const int tid  = threadIdx.x;
    const int wid  = tid >> 5;
    const int lane = tid & 31;
    const int g    = lane >> 2;
    const int q    = lane & 3;
    const int wm   = wid >> 2;
    const int wn   = wid & 3;

    const int b  = blockIdx.x >> 2;
    const int s0 = (blockIdx.x & 3) * 1024;
    const float bvv = bv[0];

    const uint32_t smA_b  = smem_u32(sA);
    const uint32_t smBT_b = smem_u32(sBT);

    auto issue = [&](int gc) {
        int mm = gc >> 3, kc = gc & 7;
        const float* src = values + ((size_t)(b * S_ + s0 + mm * 256)) * D_ + kc * 32;
        uint32_t dstb = smA_b + (gc & 1) * (ABUF_F * 4);
        #pragma unroll
        for (int it = 0; it < 4; it++) {
            int idx = tid + it * 512;
            int row = idx >> 3, f4 = idx & 7;
            cp_async16(dstb + row * ASTR_B + f4 * 16,
                       src + (size_t)row * D_ + f4 * 4);
        }
        CP_COMMIT();
    };
    issue(0);

    // stage B = W2^T [u][k], tf32-RNA-rounded
    for (int idx = tid; idx < D_ * U_; idx += 512) {
        int k = idx >> 7, u = idx & 127;
        sBT[u * BSTR + k] = __uint_as_float(rna_tf32(W2[idx]));
    }
    for (int i = tid; i < U_; i += 512) {
        sQ[i]  = g_qpb[b * U_ + i];
        sWv[i] = Wv[i];
    }
    if (tid == 0) sM[0] = -1e30f;
    __syncthreads();

    // ldmatrix addresses
    const int a_row  = wm * 64 + ((lane < 16) ? lane : (lane - 16));
    const int a_koff = (lane < 16) ? 0 : 4;
    uint32_t aoff[4];
    #pragma unroll
    for (int i = 0; i < 4; i++)
        aoff[i] = (uint32_t)((a_row + i * 16) * ASTR_B + a_koff * 4);
    const int b_row  = wn * 32 + (lane & 7) + ((lane >= 16) ? 8 : 0);
    const int b_koff = ((lane >> 3) & 1) * 4;
    uint32_t boff[2];
    #pragma unroll
    for (int j2 = 0; j2 < 2; j2++)
        boff[j2] = smBT_b + (uint32_t)((b_row + j2 * 16) * BSTR_B + b_koff * 4);

    // flash context state: thread owns float4 col dq, seq-stripe sh (32 seq)
    const int dq = tid & 63;
    const int sh = tid >> 6;
    float4 c4 = make_float4(0.f, 0.f, 0.f, 0.f);

    float acc[4][4][4];
    int gc = 0;

    for (int mt = 0; mt < NTILE; mt++) {
        #pragma unroll
        for (int i = 0; i < 4; i++)
            #pragma unroll
            for (int j = 0; j < 4; j++)
                #pragma unroll
                for (int e = 0; e < 4; e++) acc[i][j][e] = 0.0f;

        for (int kc = 0; kc < KCHUNKS; kc++, gc++) {
            CP_WAIT0();
            __syncthreads();
            if (gc + 1 < NCHUNK) issue(gc + 1);

            uint32_t aB = smA_b + (gc & 1) * (ABUF_F * 4);
            uint32_t bK = (uint32_t)(kc * 128);

            #pragma unroll
            for (int k8 = 0; k8 < 4; k8++) {
                uint32_t a[4][4];
                #pragma unroll
                for (int i = 0; i < 4; i++)
                    LDSM4(a[i], aB + aoff[i] + k8 * 32);
                uint32_t bf[2][4];
                LDSM4(bf[0], boff[0] + bK + k8 * 32);
                LDSM4(bf[1], boff[1] + bK + k8 * 32);
                #pragma unroll
                for (int j2 = 0; j2 < 2; j2++)
                    #pragma unroll
                    for (int jj = 0; jj < 2; jj++) {
                        int j = j2 * 2 + jj;
                        uint32_t b0 = bf[j2][jj * 2], b1 = bf[j2][jj * 2 + 1];
                        #pragma unroll
                        for (int i = 0; i < 4; i++)
                            mma_tf32(acc[i][j], a[i], b0, b1);
                    }
            }
        }

        // ---- score epilogue ----
        float p[8];
        #pragma unroll
        for (int e = 0; e < 8; e++) p[e] = 0.0f;
        #pragma unroll
        for (int i = 0; i < 4; i++)
            #pragma unroll
            for (int j = 0; j < 4; j++) {
                int ub = wn * 32 + j * 8 + q * 2;
                float w0 = sWv[ub], w1 = sWv[ub + 1];
                float q0 = sQ[ub],  q1 = sQ[ub + 1];
                p[i * 2]     += tanh_fast(acc[i][j][0] + q0) * w0
                              + tanh_fast(acc[i][j][1] + q1) * w1;
                p[i * 2 + 1] += tanh_fast(acc[i][j][2] + q0) * w0
                              + tanh_fast(acc[i][j][3] + q1) * w1;
            }
        #pragma unroll
        for (int e = 0; e < 8; e++) {
            p[e] += __shfl_xor_sync(0xffffffffu, p[e], 1);
            p[e] += __shfl_xor_sync(0xffffffffu, p[e], 2);
        }
        if (q == 0) {
            float* sr = sred + wn * 256 + wm * 64;
            #pragma unroll
            for (int i = 0; i < 4; i++) {
                sr[i * 16 + g]     = p[i * 2];
                sr[i * 16 + g + 8] = p[i * 2 + 1];
            }
        }
        __syncthreads();
        float myscore = 0.0f;
        if (tid < 256) {
            myscore = sred[tid] + sred[256 + tid] + sred[512 + tid] + sred[768 + tid] + bvv;
            g_score[(size_t)b * S_ + s0 + mt * 256 + tid] = myscore;
            sred[tid] = myscore;   // each thread reads its own 4 slots first; write-own-slot safe
        }
        __syncthreads();
        // block max of sred[0..255]
        for (int off = 128; off > 0; off >>= 1) {
            if (tid < off) sred[tid] = fmaxf(sred[tid], sred[tid + off]);
            __syncthreads();
        }
        float m_tile = sred[0];
        float m_old  = sM[0];
        float m_new  = fmaxf(m_old, m_tile);
        float scale  = __expf(m_old - m_new);
        if (tid < 256) sE[tid] = __expf(myscore - m_new);
        __syncthreads();
        if (tid == 0) sM[0] = m_new;

        // ---- flash context accumulation (values re-read, L2-hot) ----
        c4.x *= scale; c4.y *= scale; c4.z *= scale; c4.w *= scale;
        const float4* vsrc = (const float4*)(values +
            ((size_t)(b * S_ + s0 + mt * 256 + sh * 32)) * D_) + dq;
        const float* eb = sE + sh * 32;
        #pragma unroll 4
        for (int s = 0; s < 32; s++) {
            float ev = eb[s];
            float4 v = vsrc[(size_t)s * 64];
            c4.x += ev * v.x; c4.y += ev * v.y; c4.z += ev * v.z; c4.w += ev * v.w;
        }
        // next sE/sred write gated by chunk-loop syncthreads / epilogue syncs
    }

    // ---- combine 8 stripes, write context partial ----
    __syncthreads();
    float* sComb = sA;     // free now: 2048 floats needed
    ((float4*)sComb)[sh * 64 + dq] = c4;
    __syncthreads();
    if (tid < 256) {
        float v = 0.f;
        #pragma unroll
        for (int i = 0; i < 8; i++) v += sComb[i * 256 + tid];
        g_ctxp[(blockIdx.x & 3) * B_ * D_ + b * D_ + tid] = v;
    }
    if (tid == 0) g_mp[(blockIdx.x & 3) * B_ + b] = sM[0];
}

// ---------------------------------------------------------------------------
// K3: weights = softmax(score) per batch; also export global m, Z.
// ---------------------------------------------------------------------------
__global__ __launch_bounds__(512)
void weights_kernel(float* __restrict__ out_w) {
    int b = blockIdx.x;
    int tid = threadIdx.x;   // 512
    __shared__ float red[512];
    const float* sc = g_score + (size_t)b * S_;

    float v[8];
    float mx = -1e30f;
    #pragma unroll
    for (int k = 0; k < 8; k++) {
        v[k] = sc[tid + k * 512];
        mx = fmaxf(mx, v[k]);
    }
    red[tid] = mx;
    __syncthreads();
    for (int off = 256; off > 0; off >>= 1) {
        if (tid < off) red[tid] = fmaxf(red[tid], red[tid + off]);
        __syncthreads();
    }
    mx = red[0];
    __syncthreads();

    float sum = 0.0f;
    #pragma unroll
    for (int k = 0; k < 8; k++) {
        v[k] = __expf(v[k] - mx);
        sum += v[k];
    }
    red[tid] = sum;
    __syncthreads();
    for (int off = 256; off > 0; off >>= 1) {
        if (tid < off) red[tid] += red[tid + off];
        __syncthreads();
    }
    float Z = red[0];
    float inv = 1.0f / Z;

    if (tid == 0) { g_MZ[b] = mx; g_MZ[B_ + b] = Z; }

    float* w = out_w + (size_t)b * S_;
    #pragma unroll
    for (int k = 0; k < 8; k++)
        w[tid + k * 512] = v[k] * inv;
}

// ---------------------------------------------------------------------------
// K4: combine 4 flash partials per batch -> context
// ---------------------------------------------------------------------------
__global__ void ctx_reduce_kernel(float* __restrict__ ctx) {
    int b = blockIdx.x;
    int d = threadIdx.x;  // 256
    float m_g  = g_MZ[b];
    float invZ = 1.0f / g_MZ[B_ + b];
    float a = 0.f;
    #pragma unroll
    for (int i = 0; i < 4; i++)
        a += g_ctxp[i * B_ * D_ + b * D_ + d] * __expf(g_mp[i * B_ + b] - m_g);
    ctx[b * D_ + d] = a * invZ;
}

// ---------------------------------------------------------------------------
extern "C" void kernel_launch(void* const* d_in, const int* in_sizes, int n_in,
                              void* d_out, int out_size) {
    const float* query  = (const float*)d_in[0];
    const float* values = (const float*)d_in[1];
    const float* W1     = (const float*)d_in[2];
    const float* b1     = (const float*)d_in[3];
    const float* W2     = (const float*)d_in[4];
    const float* b2     = (const float*)d_in[5];
    const float* Wv     = (const float*)d_in[6];
    const float* bv     = (const float*)d_in[7];

    float* out  = (float*)d_out;
    float* ctx  = out;             // [B, D]
    float* wout = out + B_ * D_;   // [B, S, 1]

    cudaFuncSetAttribute(score_mma_kernel,
                         cudaFuncAttributeMaxDynamicSharedMemorySize, SMEM_SC);

    qproj_kernel<<<B_, U_>>>(query, W1, b1, b2);
    score_mma_kernel<<<B_ * 4, 512, SMEM_SC>>>(values, W2, Wv, bv);
    weights_kernel<<<B_, 512>>>(wout);
    ctx_reduce_kernel<<<B_, 256>>>(ctx);
}

// round 8
// speedup vs baseline: 4.7526x; 1.1644x over previous
#include <cuda_runtime.h>
#include <cstdint>
#include <math.h>

#define B_ 128
#define S_ 4096
#define D_ 256
#define U_ 128

#define NSPLIT 8          // 512-seq units per batch
#define GRID_SC 148       // persistent CTAs (1 per SM, safe lower bound)
#define NUNIT (B_ * NSPLIT)   // 1024 work units

// ---------------- device scratch (no allocs allowed) ----------------
__device__ float g_qpb[B_ * U_];                  // q@W1 + b1 + b2
__device__ float g_score[B_ * S_];                // pre-softmax scores
__device__ float g_ctxp[NSPLIT * B_ * D_];        // flash context partials
__device__ float g_mp[NSPLIT * B_];               // per-split max
__device__ float g_zp[NSPLIT * B_];               // per-split expsum
__device__ float g_MZ[2 * B_];                    // global [m | Z] per batch

// ---------------- helpers ----------------
__device__ __forceinline__ uint32_t smem_u32(const void* p) {
    uint32_t a;
    asm("{ .reg .u64 t; cvta.to.shared.u64 t, %1; cvt.u32.u64 %0, t; }" : "=r"(a) : "l"(p));
    return a;
}
__device__ __forceinline__ void cp_async16(uint32_t dst, const void* src) {
    asm volatile("cp.async.cg.shared.global [%0], [%1], 16;" :: "r"(dst), "l"(src));
}
#define CP_COMMIT() asm volatile("cp.async.commit_group;" ::: "memory")
#define CP_WAIT0()  asm volatile("cp.async.wait_group 0;" ::: "memory")

__device__ __forceinline__ uint32_t rna_tf32(float f) {
    uint32_t r;
    asm("cvt.rna.tf32.f32 %0, %1;" : "=r"(r) : "f"(f));
    return r;
}

#define LDSM4(r, addr) \
    asm volatile("ldmatrix.sync.aligned.m8n8.x4.shared.b16 {%0,%1,%2,%3}, [%4];" \
        : "=r"((r)[0]), "=r"((r)[1]), "=r"((r)[2]), "=r"((r)[3]) : "r"(addr))

__device__ __forceinline__ void mma_tf32(float* d, const uint32_t* a,
                                         uint32_t b0, uint32_t b1) {
    asm volatile(
        "mma.sync.aligned.m16n8k8.row.col.f32.tf32.tf32.f32 "
        "{%0,%1,%2,%3}, {%4,%5,%6,%7}, {%8,%9}, {%0,%1,%2,%3};"
        : "+f"(d[0]), "+f"(d[1]), "+f"(d[2]), "+f"(d[3])
        : "r"(a[0]), "r"(a[1]), "r"(a[2]), "r"(a[3]), "r"(b0), "r"(b1));
}

__device__ __forceinline__ float tanh_fast(float x) {
    float ax = fabsf(x);
    float e  = __expf(ax + ax);
    float t  = 1.0f - __fdividef(2.0f, e + 1.0f);
    return copysignf(t, x);
}

// ---------------------------------------------------------------------------
// K1: qpb[b,u] = query[b,:]@W1[:,u] + b1[u] + b2[u]
// ---------------------------------------------------------------------------
__global__ void qproj_kernel(const float* __restrict__ query,
                             const float* __restrict__ W1,
                             const float* __restrict__ b1,
                             const float* __restrict__ b2) {
    int b = blockIdx.x;
    int u = threadIdx.x;
    __shared__ float sq[D_];
    for (int i = threadIdx.x; i < D_; i += blockDim.x) sq[i] = query[b * D_ + i];
    __syncthreads();
    float acc = b1[u] + b2[u];
    #pragma unroll 8
    for (int d = 0; d < D_; d++) acc += sq[d] * W1[d * U_ + u];
    g_qpb[b * U_ + u] = acc;
}

// ---------------------------------------------------------------------------
// K2: PERSISTENT fused score + flash-context kernel.
//   Grid = 148 CTAs, each stride-loops units of 512 seq (2 tiles of 256).
//   512 threads = 16 warps, 4(M)x4(N), warp tile 64x32, tf32 mma + ldmatrix.
// ---------------------------------------------------------------------------
#define ASTR_B  144
#define BSTR    260
#define BSTR_B  1040
#define ABUF_F  (256 * 36)                      // 9216 floats per buffer
// floats: sQ 128 | sWv 128 | sred 1024 | sE 256 | swA 16 | swB 16
#define OFF_E_F 1280
#define OFF_W_F 1536
#define OFF_A_F 1568
#define OFF_B_F (OFF_A_F + 2 * ABUF_F)          // 20000
#define SMEM_F  (OFF_B_F + U_ * BSTR)           // 53280 floats
#define SMEM_SC (SMEM_F * 4)                    // 213120 bytes

#define NTILE   2
#define KCHUNKS 8
#define NCHUNK  (NTILE * KCHUNKS)   // 16 per unit

__global__ __launch_bounds__(512, 1)
void score_mma_kernel(const float* __restrict__ values,
                      const float* __restrict__ W2,
                      const float* __restrict__ Wv,
                      const float* __restrict__ bv) {
    extern __shared__ float sm[];
    float* sQ   = sm;
    float* sWv  = sm + 128;
    float* sred = sm + 256;          // 1024 floats
    float* sE   = sm + OFF_E_F;      // 256 floats
    float* swA  = sm + OFF_W_F;      // 16
    float* swB  = sm + OFF_W_F + 16; // 16
    float* sA   = sm + OFF_A_F;
    float* sBT  = sm + OFF_B_F;

    const int tid  = threadIdx.x;
    const int wid  = tid >> 5;
    const int lane = tid & 31;
    const int g    = lane >> 2;
    const int q    = lane & 3;
    const int wm   = wid >> 2;
    const int wn   = wid & 3;
    const float bvv = bv[0];

    const uint32_t smA_b  = smem_u32(sA);
    const uint32_t smBT_b = smem_u32(sBT);

    // ---- one-time staging: B = W2^T [u][k] tf32-RNA, Wv ----
    for (int idx = tid; idx < D_ * U_; idx += 512) {
        int k = idx >> 7, u = idx & 127;
        sBT[u * BSTR + k] = __uint_as_float(rna_tf32(W2[idx]));
    }
    for (int i = tid; i < U_; i += 512) sWv[i] = Wv[i];

    // ldmatrix per-thread offsets
    const int a_row  = wm * 64 + ((lane < 16) ? lane : (lane - 16));
    const int a_koff = (lane < 16) ? 0 : 4;
    uint32_t aoff[4];
    #pragma unroll
    for (int i = 0; i < 4; i++)
        aoff[i] = (uint32_t)((a_row + i * 16) * ASTR_B + a_koff * 4);
    const int b_row  = wn * 32 + (lane & 7) + ((lane >= 16) ? 8 : 0);
    const int b_koff = ((lane >> 3) & 1) * 4;
    uint32_t boff[2];
    #pragma unroll
    for (int j2 = 0; j2 < 2; j2++)
        boff[j2] = smBT_b + (uint32_t)((b_row + j2 * 16) * BSTR_B + b_koff * 4);

    const int dq = tid & 63;   // float4 column of context
    const int sh = tid >> 6;   // seq stripe (32 rows)

    // ================= persistent unit loop =================
    for (int unit = blockIdx.x; unit < NUNIT; unit += GRID_SC) {
        const int b  = unit >> 3;
        const int ss = unit & 7;
        const int s0 = ss * 512;

        auto issue = [&](int gc) {
            int mm = gc >> 3, kc = gc & 7;
            const float* src = values + ((size_t)(b * S_ + s0 + mm * 256)) * D_ + kc * 32;
            uint32_t dstb = smA_b + (gc & 1) * (ABUF_F * 4);
            #pragma unroll
            for (int it = 0; it < 4; it++) {
                int idx = tid + it * 512;
                int row = idx >> 3, f4 = idx & 7;
                cp_async16(dstb + row * ASTR_B + f4 * 16,
                           src + (size_t)row * D_ + f4 * 4);
            }
            CP_COMMIT();
        };
        issue(0);
        for (int i = tid; i < U_; i += 512) sQ[i] = g_qpb[b * U_ + i];
        // sQ/first-chunk visibility ordered by first CP_WAIT0+__syncthreads

        float m_run = -1e30f, z_run = 0.0f;
        float4 c4 = make_float4(0.f, 0.f, 0.f, 0.f);

        float acc[4][4][4];
        int gc = 0;

        for (int mt = 0; mt < NTILE; mt++) {
            #pragma unroll
            for (int i = 0; i < 4; i++)
                #pragma unroll
                for (int j = 0; j < 4; j++)
                    #pragma unroll
                    for (int e = 0; e < 4; e++) acc[i][j][e] = 0.0f;

            for (int kc = 0; kc < KCHUNKS; kc++, gc++) {
                CP_WAIT0();
                __syncthreads();
                if (gc + 1 < NCHUNK) issue(gc + 1);

                uint32_t aB = smA_b + (gc & 1) * (ABUF_F * 4);
                uint32_t bK = (uint32_t)(kc * 128);

                #pragma unroll
                for (int k8 = 0; k8 < 4; k8++) {
                    uint32_t a[4][4];
                    #pragma unroll
                    for (int i = 0; i < 4; i++)
                        LDSM4(a[i], aB + aoff[i] + k8 * 32);
                    uint32_t bf[2][4];
                    LDSM4(bf[0], boff[0] + bK + k8 * 32);
                    LDSM4(bf[1], boff[1] + bK + k8 * 32);
                    #pragma unroll
                    for (int j2 = 0; j2 < 2; j2++)
                        #pragma unroll
                        for (int jj = 0; jj < 2; jj++) {
                            int j = j2 * 2 + jj;
                            uint32_t b0 = bf[j2][jj * 2], b1 = bf[j2][jj * 2 + 1];
                            #pragma unroll
                            for (int i = 0; i < 4; i++)
                                mma_tf32(acc[i][j], a[i], b0, b1);
                        }
                }
            }

            // ---- score epilogue ----
            float p[8];
            #pragma unroll
            for (int e = 0; e < 8; e++) p[e] = 0.0f;
            #pragma unroll
            for (int i = 0; i < 4; i++)
                #pragma unroll
                for (int j = 0; j < 4; j++) {
                    int ub = wn * 32 + j * 8 + q * 2;
                    float w0 = sWv[ub], w1 = sWv[ub + 1];
                    float q0 = sQ[ub],  q1 = sQ[ub + 1];
                    p[i * 2]     += tanh_fast(acc[i][j][0] + q0) * w0
                                  + tanh_fast(acc[i][j][1] + q1) * w1;
                    p[i * 2 + 1] += tanh_fast(acc[i][j][2] + q0) * w0
                                  + tanh_fast(acc[i][j][3] + q1) * w1;
                }
            #pragma unroll
            for (int e = 0; e < 8; e++) {
                p[e] += __shfl_xor_sync(0xffffffffu, p[e], 1);
                p[e] += __shfl_xor_sync(0xffffffffu, p[e], 2);
            }
            if (q == 0) {
                float* sr = sred + wn * 256 + wm * 64;
                #pragma unroll
                for (int i = 0; i < 4; i++) {
                    sr[i * 16 + g]     = p[i * 2];
                    sr[i * 16 + g + 8] = p[i * 2 + 1];
                }
            }
            __syncthreads();

            float myscore = -1e30f;
            if (tid < 256) {
                myscore = sred[tid] + sred[256 + tid] + sred[512 + tid] + sred[768 + tid] + bvv;
                g_score[(size_t)b * S_ + s0 + mt * 256 + tid] = myscore;
            }
            // warp-shuffle max -> 16 partials
            float lm = myscore;
            #pragma unroll
            for (int off = 16; off > 0; off >>= 1)
                lm = fmaxf(lm, __shfl_xor_sync(0xffffffffu, lm, off));
            if (lane == 0) swA[wid] = lm;
            __syncthreads();
            float m_tile = -1e30f;
            #pragma unroll
            for (int i = 0; i < 16; i++) m_tile = fmaxf(m_tile, swA[i]);
            float m_new  = fmaxf(m_run, m_tile);
            float scale  = __expf(m_run - m_new);
            m_run = m_new;

            float e = 0.0f;
            if (tid < 256) {
                e = __expf(myscore - m_new);
                sE[tid] = e;
            }
            float ls = e;
            #pragma unroll
            for (int off = 16; off > 0; off >>= 1)
                ls += __shfl_xor_sync(0xffffffffu, ls, off);
            if (lane == 0) swB[wid] = ls;
            __syncthreads();
            float z_tile = 0.0f;
            #pragma unroll
            for (int i = 0; i < 16; i++) z_tile += swB[i];
            z_run = z_run * scale + z_tile;

            // ---- flash context accumulation (values re-read, L2-hot) ----
            c4.x *= scale; c4.y *= scale; c4.z *= scale; c4.w *= scale;
            const float4* vsrc = (const float4*)(values +
                ((size_t)(b * S_ + s0 + mt * 256 + sh * 32)) * D_) + dq;
            const float* eb = sE + sh * 32;
            #pragma unroll 4
            for (int s = 0; s < 32; s++) {
                float ev = eb[s];
                float4 v = vsrc[(size_t)s * 64];
                c4.x += ev * v.x; c4.y += ev * v.y; c4.z += ev * v.z; c4.w += ev * v.w;
            }
        }

        // ---- combine 8 stripes via sred (1024 floats, two rounds) ----
        __syncthreads();
        if (sh < 4) ((float4*)sred)[sh * 64 + dq] = c4;
        __syncthreads();
        float v = 0.0f;
        if (tid < 256) {
            #pragma unroll
            for (int i = 0; i < 4; i++) v += sred[i * 256 + tid];
        }
        __syncthreads();
        if (sh >= 4) ((float4*)sred)[(sh - 4) * 64 + dq] = c4;
        __syncthreads();
        if (tid < 256) {
            #pragma unroll
            for (int i = 0; i < 4; i++) v += sred[i * 256 + tid];
            g_ctxp[(size_t)ss * B_ * D_ + b * D_ + tid] = v;
        }
        if (tid == 0) {
            g_mp[ss * B_ + b] = m_run;
            g_zp[ss * B_ + b] = z_run;
        }
        __syncthreads();   // protect sQ/sred before next unit
    }
}

// ---------------------------------------------------------------------------
// K3: combine flash partials -> context; derive global (m, Z) per batch.
// ---------------------------------------------------------------------------
__global__ void ctx_reduce_kernel(float* __restrict__ ctx) {
    int b = blockIdx.x;
    int d = threadIdx.x;  // 256
    float m = -1e30f;
    #pragma unroll
    for (int i = 0; i < NSPLIT; i++) m = fmaxf(m, g_mp[i * B_ + b]);
    float Z = 0.0f;
    #pragma unroll
    for (int i = 0; i < NSPLIT; i++) Z += g_zp[i * B_ + b] * __expf(g_mp[i * B_ + b] - m);
    if (d == 0) { g_MZ[b] = m; g_MZ[B_ + b] = Z; }
    float a = 0.0f;
    #pragma unroll
    for (int i = 0; i < NSPLIT; i++)
        a += g_ctxp[(size_t)i * B_ * D_ + b * D_ + d] * __expf(g_mp[i * B_ + b] - m);
    ctx[b * D_ + d] = a / Z;
}

// ---------------------------------------------------------------------------
// K4: weights[s] = exp(score[s] - m_b) / Z_b  (fully parallel rescale)
// ---------------------------------------------------------------------------
__global__ __launch_bounds__(256)
void weights_kernel(float* __restrict__ out_w) {
    int idx = blockIdx.x * 256 + threadIdx.x;   // 524288 total
    int b = idx >> 12;
    float m = g_MZ[b];
    float invZ = __frcp_rn(g_MZ[B_ + b]);
    out_w[idx] = __expf(g_score[idx] - m) * invZ;
}

// ---------------------------------------------------------------------------
extern "C" void kernel_launch(void* const* d_in, const int* in_sizes, int n_in,
                              void* d_out, int out_size) {
    const float* query  = (const float*)d_in[0];
    const float* values = (const float*)d_in[1];
    const float* W1     = (const float*)d_in[2];
    const float* b1     = (const float*)d_in[3];
    const float* W2     = (const float*)d_in[4];
    const float* b2     = (const float*)d_in[5];
    const float* Wv     = (const float*)d_in[6];
    const float* bv     = (const float*)d_in[7];

    float* out  = (float*)d_out;
    float* ctx  = out;             // [B, D]
    float* wout = out + B_ * D_;   // [B, S, 1]

    cudaFuncSetAttribute(score_mma_kernel,
                         cudaFuncAttributeMaxDynamicSharedMemorySize, SMEM_SC);

    qproj_kernel<<<B_, U_>>>(query, W1, b1, b2);
    score_mma_kernel<<<GRID_SC, 512, SMEM_SC>>>(values, W2, Wv, bv);
    ctx_reduce_kernel<<<B_, 256>>>(ctx);
    weights_kernel<<<(B_ * S_) / 256, 256>>>(wout);
}

// round 11
// speedup vs baseline: 5.0704x; 1.0669x over previous
#include <cuda_runtime.h>
#include <cuda_fp16.h>
#include <cstdint>
#include <math.h>

#define B_ 128
#define S_ 4096
#define D_ 256
#define U_ 128

#define NSPLIT 8
#define GRID_SC 148
#define NUNIT (B_ * NSPLIT)

// ---------------- device scratch ----------------
__device__ float g_qpb[B_ * U_];
__device__ float g_score[B_ * S_];
__device__ float g_ctxp[NSPLIT * B_ * D_];
__device__ float g_mp[NSPLIT * B_];
__device__ float g_zp[NSPLIT * B_];
__device__ float g_MZ[2 * B_];

// ---------------- helpers ----------------
__device__ __forceinline__ uint32_t smem_u32(const void* p) {
    uint32_t a;
    asm("{ .reg .u64 t; cvta.to.shared.u64 t, %1; cvt.u32.u64 %0, t; }" : "=r"(a) : "l"(p));
    return a;
}
__device__ __forceinline__ void cp_async16(uint32_t dst, const void* src) {
    asm volatile("cp.async.cg.shared.global [%0], [%1], 16;" :: "r"(dst), "l"(src));
}
#define CP_COMMIT()  asm volatile("cp.async.commit_group;" ::: "memory")
#define CP_WAIT(n)   asm volatile("cp.async.wait_group %0;" :: "n"(n) : "memory")

#define LDSM4(r, addr) \
    asm volatile("ldmatrix.sync.aligned.m8n8.x4.shared.b16 {%0,%1,%2,%3}, [%4];" \
        : "=r"((r)[0]), "=r"((r)[1]), "=r"((r)[2]), "=r"((r)[3]) : "r"(addr))

// m16n8k16 fp16 MMA, fp32 accum
__device__ __forceinline__ void mma_f16(float* d, const uint32_t* a,
                                        uint32_t b0, uint32_t b1) {
    asm volatile(
        "mma.sync.aligned.m16n8k16.row.col.f32.f16.f16.f32 "
        "{%0,%1,%2,%3}, {%4,%5,%6,%7}, {%8,%9}, {%0,%1,%2,%3};"
        : "+f"(d[0]), "+f"(d[1]), "+f"(d[2]), "+f"(d[3])
        : "r"(a[0]), "r"(a[1]), "r"(a[2]), "r"(a[3]), "r"(b0), "r"(b1));
}

__device__ __forceinline__ float tanh_fast(float x) {
    float ax = fabsf(x);
    float e  = __expf(ax + ax);
    float t  = 1.0f - __fdividef(2.0f, e + 1.0f);
    return copysignf(t, x);
}

// ---------------------------------------------------------------------------
// K1: qpb[b,u] = query[b,:]@W1[:,u] + b1[u] + b2[u]
// ---------------------------------------------------------------------------
__global__ void qproj_kernel(const float* __restrict__ query,
                             const float* __restrict__ W1,
                             const float* __restrict__ b1,
                             const float* __restrict__ b2) {
    int b = blockIdx.x;
    int u = threadIdx.x;
    __shared__ float sq[D_];
    for (int i = threadIdx.x; i < D_; i += blockDim.x) sq[i] = query[b * D_ + i];
    __syncthreads();
    float acc = b1[u] + b2[u];
    #pragma unroll 8
    for (int d = 0; d < D_; d++) acc += sq[d] * W1[d * U_ + u];
    g_qpb[b * U_ + u] = acc;
}

// ---------------------------------------------------------------------------
// K2: PERSISTENT fused score + flash-context, fp16 m16n8k16 mma.
//   148 CTAs x 512 thr (16 warps, 4Mx4N, warp tile 64x32).
//   Unit = 512 seq (2 tiles x 256). Chunk = 256 rows x 32 k.
//   fp32 staging ring (cp.async) -> per-thread cvt -> fp16 MMA buffers.
// ---------------------------------------------------------------------------
#define SSTR_F   36            // staging row stride (floats) = 144B
#define SBUF_F   (256 * SSTR_F)        // 9216 floats / buffer
#define AH_STR   80            // fp16 A row stride bytes
#define AH_BUF_B (256 * AH_STR)        // 20480 B / buffer
#define BH_STR   528           // fp16 B row stride bytes (264 halfs)

#define OFF_E_F   1280
#define OFF_W_F   1536
#define OFF_STG_F 1600
#define OFF_AH_F  (OFF_STG_F + 2 * SBUF_F)        // 20032
#define OFF_BH_F  (OFF_AH_F + (2 * AH_BUF_B) / 4) // 30272
#define SMEM_F    (OFF_BH_F + (U_ * BH_STR) / 4)  // 47168 floats
#define SMEM_SC   (SMEM_F * 4)                    // 188672 bytes

#define NTILE   2
#define KCHUNKS 8
#define NCHUNK  (NTILE * KCHUNKS)   // 16

__global__ __launch_bounds__(512, 1)
void score_mma_kernel(const float* __restrict__ values,
                      const float* __restrict__ W2,
                      const float* __restrict__ Wv,
                      const float* __restrict__ bv) {
    extern __shared__ float sm[];
    float* sQ   = sm;
    float* sWv  = sm + 128;
    float* sred = sm + 256;
    float* sE   = sm + OFF_E_F;
    float* swA  = sm + OFF_W_F;
    float* swB  = sm + OFF_W_F + 16;
    float* sStg = sm + OFF_STG_F;
    char*  sAh  = (char*)sm + OFF_AH_F * 4;
    __half* sBTh = (__half*)(sm + OFF_BH_F);

    const int tid  = threadIdx.x;
    const int wid  = tid >> 5;
    const int lane = tid & 31;
    const int g    = lane >> 2;
    const int q    = lane & 3;
    const int wm   = wid >> 2;
    const int wn   = wid & 3;
    const float bvv = bv[0];

    const uint32_t smStg_b = smem_u32(sStg);
    const uint32_t smAh_b  = smem_u32(sAh);
    const uint32_t smBh_b  = smem_u32(sBTh);

    // ---- one-time: B = W2^T fp16 [u][k], Wv ----
    for (int idx = tid; idx < D_ * U_; idx += 512) {
        int k = idx >> 7, u = idx & 127;
        sBTh[u * 264 + k] = __float2half_rn(W2[idx]);
    }
    for (int i = tid; i < U_; i += 512) sWv[i] = Wv[i];

    // ---- ldmatrix per-thread offsets ----
    // A (16x16 fp16): m0 rows0-7 k0-7 | m1 rows8-15 k0-7 | m2 rows0-7 k8-15 | m3 rows8-15 k8-15
    const int a_r  = (lane & 7) + (((lane >> 3) & 1) * 8);
    const int a_kb = (lane >= 16) ? 16 : 0;
    uint32_t aoff[4];
    #pragma unroll
    for (int i = 0; i < 4; i++)
        aoff[i] = (uint32_t)((wm * 64 + i * 16 + a_r) * AH_STR + a_kb);
    // B from BT[u][k]: m0 u0-7 k0-7 | m1 u0-7 k8-15 | m2 u8-15 k0-7 | m3 u8-15 k8-15
    const int b_r  = (lane & 7) + ((lane >= 16) ? 8 : 0);
    const int b_kb = ((lane >> 3) & 1) * 16;
    uint32_t boff[2];
    #pragma unroll
    for (int jt = 0; jt < 2; jt++)
        boff[jt] = smBh_b + (uint32_t)((wn * 32 + jt * 16 + b_r) * BH_STR + b_kb);

    const int dq = tid & 63;
    const int sh = tid >> 6;

    // ================= persistent unit loop =================
    for (int unit = blockIdx.x; unit < NUNIT; unit += GRID_SC) {
        const int b  = unit >> 3;
        const int ss = unit & 7;
        const int s0 = ss * 512;

        auto issue = [&](int gc) {
            int mm = gc >> 3, kc = gc & 7;
            const float* src = values + ((size_t)(b * S_ + s0 + mm * 256)) * D_ + kc * 32;
            uint32_t dstb = smStg_b + (gc & 1) * (SBUF_F * 4);
            #pragma unroll
            for (int it = 0; it < 4; it++) {
                int idx = tid + it * 512;
                int row = idx >> 3, f4 = idx & 7;
                cp_async16(dstb + row * 144 + f4 * 16,
                           src + (size_t)row * D_ + f4 * 4);
            }
            CP_COMMIT();
        };
        // convert chunk c: fp32 staging -> fp16 A buffer (thread converts its own copies)
        auto convert = [&](int c) {
            const float* sbuf = sStg + (c & 1) * SBUF_F;
            char* abuf = sAh + (c & 1) * AH_BUF_B;
            #pragma unroll
            for (int it = 0; it < 4; it++) {
                int idx = tid + it * 512;
                int row = idx >> 3, f4 = idx & 7;
                float4 v = *reinterpret_cast<const float4*>(sbuf + row * SSTR_F + f4 * 4);
                __half2 h0 = __floats2half2_rn(v.x, v.y);
                __half2 h1 = __floats2half2_rn(v.z, v.w);
                uint2 pk;
                pk.x = *reinterpret_cast<uint32_t*>(&h0);
                pk.y = *reinterpret_cast<uint32_t*>(&h1);
                *reinterpret_cast<uint2*>(abuf + row * AH_STR + f4 * 8) = pk;
            }
        };

        // prologue
        issue(0);
        issue(1);
        for (int i = tid; i < U_; i += 512) sQ[i] = g_qpb[b * U_ + i];
        CP_WAIT(1);
        convert(0);
        __syncthreads();

        float m_run = -1e30f, z_run = 0.0f;
        float4 c4 = make_float4(0.f, 0.f, 0.f, 0.f);

        float acc[4][4][4];

        for (int gc = 0; gc < NCHUNK; gc++) {
            if ((gc & 7) == 0) {
                #pragma unroll
                for (int i = 0; i < 4; i++)
                    #pragma unroll
                    for (int j = 0; j < 4; j++)
                        #pragma unroll
                        for (int e = 0; e < 4; e++) acc[i][j][e] = 0.0f;
            }

            if (gc + 2 < NCHUNK) issue(gc + 2);
            if (gc + 1 < NCHUNK) {
                if (gc + 2 < NCHUNK) { CP_WAIT(1); } else { CP_WAIT(0); }
                convert(gc + 1);
            }

            // ---- MMA on chunk gc (B panel at k = (gc&7)*32 -> byte offset *64) ----
            {
                uint32_t aB = smAh_b + (gc & 1) * AH_BUF_B;
                uint32_t bK = (uint32_t)((gc & 7) * 64);
                #pragma unroll
                for (int k16 = 0; k16 < 2; k16++) {
                    uint32_t a[4][4];
                    #pragma unroll
                    for (int i = 0; i < 4; i++)
                        LDSM4(a[i], aB + aoff[i] + k16 * 32);
                    uint32_t bf[2][4];
                    LDSM4(bf[0], boff[0] + bK + k16 * 32);
                    LDSM4(bf[1], boff[1] + bK + k16 * 32);
                    #pragma unroll
                    for (int j = 0; j < 4; j++) {
                        uint32_t b0 = bf[j >> 1][(j & 1) * 2];
                        uint32_t b1 = bf[j >> 1][(j & 1) * 2 + 1];
                        #pragma unroll
                        for (int i = 0; i < 4; i++)
                            mma_f16(acc[i][j], a[i], b0, b1);
                    }
                }
            }

            if ((gc & 7) != 7) {
                __syncthreads();
                continue;
            }

            // ======== tile epilogue (gc&7==7), mt = gc>>3 ========
            const int mt = gc >> 3;
            float p[8];
            #pragma unroll
            for (int e = 0; e < 8; e++) p[e] = 0.0f;
            #pragma unroll
            for (int i = 0; i < 4; i++)
                #pragma unroll
                for (int j = 0; j < 4; j++) {
                    int ub = wn * 32 + j * 8 + q * 2;
                    float w0 = sWv[ub], w1 = sWv[ub + 1];
                    float q0 = sQ[ub],  q1 = sQ[ub + 1];
                    p[i * 2]     += tanh_fast(acc[i][j][0] + q0) * w0
                                  + tanh_fast(acc[i][j][1] + q1) * w1;
                    p[i * 2 + 1] += tanh_fast(acc[i][j][2] + q0) * w0
                                  + tanh_fast(acc[i][j][3] + q1) * w1;
                }
            #pragma unroll
            for (int e = 0; e < 8; e++) {
                p[e] += __shfl_xor_sync(0xffffffffu, p[e], 1);
                p[e] += __shfl_xor_sync(0xffffffffu, p[e], 2);
            }
            __syncthreads();   // all MMA/convert done; sred free
            if (q == 0) {
                float* sr = sred + wn * 256 + wm * 64;
                #pragma unroll
                for (int i = 0; i < 4; i++) {
                    sr[i * 16 + g]     = p[i * 2];
                    sr[i * 16 + g + 8] = p[i * 2 + 1];
                }
            }
            __syncthreads();

            float myscore = -1e30f;
            if (tid < 256) {
                myscore = sred[tid] + sred[256 + tid] + sred[512 + tid] + sred[768 + tid] + bvv;
                g_score[(size_t)b * S_ + s0 + mt * 256 + tid] = myscore;
            }
            float lm = myscore;
            #pragma unroll
            for (int off = 16; off > 0; off >>= 1)
                lm = fmaxf(lm, __shfl_xor_sync(0xffffffffu, lm, off));
            if (lane == 0) swA[wid] = lm;
            __syncthreads();
            float m_tile = -1e30f;
            #pragma unroll
            for (int i = 0; i < 16; i++) m_tile = fmaxf(m_tile, swA[i]);
            float m_new  = fmaxf(m_run, m_tile);
            float scale  = __expf(m_run - m_new);
            m_run = m_new;

            float e = 0.0f;
            if (tid < 256) {
                e = __expf(myscore - m_new);
                sE[tid] = e;
            }
            float ls = e;
            #pragma unroll
            for (int off = 16; off > 0; off >>= 1)
                ls += __shfl_xor_sync(0xffffffffu, ls, off);
            if (lane == 0) swB[wid] = ls;
            __syncthreads();
            float z_tile = 0.0f;
            #pragma unroll
            for (int i = 0; i < 16; i++) z_tile += swB[i];
            z_run = z_run * scale + z_tile;

            // flash context accumulation (values L2-hot)
            c4.x *= scale; c4.y *= scale; c4.z *= scale; c4.w *= scale;
            const float4* vsrc = (const float4*)(values +
                ((size_t)(b * S_ + s0 + mt * 256 + sh * 32)) * D_) + dq;
            const float* eb = sE + sh * 32;
            #pragma unroll 4
            for (int s = 0; s < 32; s++) {
                float ev = eb[s];
                float4 v = vsrc[(size_t)s * 64];
                c4.x += ev * v.x; c4.y += ev * v.y; c4.z += ev * v.z; c4.w += ev * v.w;
            }
        }

        // ---- combine 8 stripes via sred ----
        __syncthreads();
        if (sh < 4) ((float4*)sred)[sh * 64 + dq] = c4;
        __syncthreads();
        float v = 0.0f;
        if (tid < 256) {
            #pragma unroll
            for (int i = 0; i < 4; i++) v += sred[i * 256 + tid];
        }
        __syncthreads();
        if (sh >= 4) ((float4*)sred)[(sh - 4) * 64 + dq] = c4;
        __syncthreads();
        if (tid < 256) {
            #pragma unroll
            for (int i = 0; i < 4; i++) v += sred[i * 256 + tid];
            g_ctxp[(size_t)ss * B_ * D_ + b * D_ + tid] = v;
        }
        if (tid == 0) {
            g_mp[ss * B_ + b] = m_run;
            g_zp[ss * B_ + b] = z_run;
        }
        __syncthreads();
    }
}

// ---------------------------------------------------------------------------
// K3: combine flash partials -> context; derive global (m, Z).
// ---------------------------------------------------------------------------
__global__ void ctx_reduce_kernel(float* __restrict__ ctx) {
    int b = blockIdx.x;
    int d = threadIdx.x;  // 256
    float m = -1e30f;
    #pragma unroll
    for (int i = 0; i < NSPLIT; i++) m = fmaxf(m, g_mp[i * B_ + b]);
    float Z = 0.0f;
    #pragma unroll
    for (int i = 0; i < NSPLIT; i++) Z += g_zp[i * B_ + b] * __expf(g_mp[i * B_ + b] - m);
    if (d == 0) { g_MZ[b] = m; g_MZ[B_ + b] = Z; }
    float a = 0.0f;
    #pragma unroll
    for (int i = 0; i < NSPLIT; i++)
        a += g_ctxp[(size_t)i * B_ * D_ + b * D_ + d] * __expf(g_mp[i * B_ + b] - m);
    ctx[b * D_ + d] = a / Z;
}

// ---------------------------------------------------------------------------
// K4: weights[s] = exp(score[s] - m_b) / Z_b
// ---------------------------------------------------------------------------
__global__ __launch_bounds__(256)
void weights_kernel(float* __restrict__ out_w) {
    int idx = blockIdx.x * 256 + threadIdx.x;
    int b = idx >> 12;
    float m = g_MZ[b];
    float invZ = __frcp_rn(g_MZ[B_ + b]);
    out_w[idx] = __expf(g_score[idx] - m) * invZ;
}

// ---------------------------------------------------------------------------
extern "C" void kernel_launch(void* const* d_in, const int* in_sizes, int n_in,
                              void* d_out, int out_size) {
    const float* query  = (const float*)d_in[0];
    const float* values = (const float*)d_in[1];
    const float* W1     = (const float*)d_in[2];
    const float* b1     = (const float*)d_in[3];
    const float* W2     = (const float*)d_in[4];
    const float* b2     = (const float*)d_in[5];
    const float* Wv     = (const float*)d_in[6];
    const float* bv     = (const float*)d_in[7];

    float* out  = (float*)d_out;
    float* ctx  = out;
    float* wout = out + B_ * D_;

    cudaFuncSetAttribute(score_mma_kernel,
                         cudaFuncAttributeMaxDynamicSharedMemorySize, SMEM_SC);

    qproj_kernel<<<B_, U_>>>(query, W1, b1, b2);
    score_mma_kernel<<<GRID_SC, 512, SMEM_SC>>>(values, W2, Wv, bv);
    ctx_reduce_kernel<<<B_, 256>>>(ctx);
    weights_kernel<<<(B_ * S_) / 256, 256>>>(wout);
}

// round 12
// speedup vs baseline: 5.7148x; 1.1271x over previous
#include <cuda_runtime.h>
#include <cuda_fp16.h>
#include <cstdint>
#include <math.h>

#define B_ 128
#define S_ 4096
#define D_ 256
#define U_ 128

#define NSPLIT 8
#define GRID_SC 148
#define NUNIT (B_ * NSPLIT)

// ---------------- device scratch ----------------
__device__ float g_qpb[B_ * U_];
__device__ float g_score[B_ * S_];
__device__ float g_ctxp[NSPLIT * B_ * D_];
__device__ float g_mp[NSPLIT * B_];
__device__ float g_zp[NSPLIT * B_];
__device__ float g_MZ[2 * B_];

// ---------------- helpers ----------------
__device__ __forceinline__ uint32_t smem_u32(const void* p) {
    uint32_t a;
    asm("{ .reg .u64 t; cvta.to.shared.u64 t, %1; cvt.u32.u64 %0, t; }" : "=r"(a) : "l"(p));
    return a;
}

#define LDSM4(r, addr) \
    asm volatile("ldmatrix.sync.aligned.m8n8.x4.shared.b16 {%0,%1,%2,%3}, [%4];" \
        : "=r"((r)[0]), "=r"((r)[1]), "=r"((r)[2]), "=r"((r)[3]) : "r"(addr))

// m16n8k16 fp16 MMA, fp32 accum
__device__ __forceinline__ void mma_f16(float* d, const uint32_t* a,
                                        uint32_t b0, uint32_t b1) {
    asm volatile(
        "mma.sync.aligned.m16n8k16.row.col.f32.f16.f16.f32 "
        "{%0,%1,%2,%3}, {%4,%5,%6,%7}, {%8,%9}, {%0,%1,%2,%3};"
        : "+f"(d[0]), "+f"(d[1]), "+f"(d[2]), "+f"(d[3])
        : "r"(a[0]), "r"(a[1]), "r"(a[2]), "r"(a[3]), "r"(b0), "r"(b1));
}

__device__ __forceinline__ float tanh_fast(float x) {
    float ax = fabsf(x);
    float e  = __expf(ax + ax);
    float t  = 1.0f - __fdividef(2.0f, e + 1.0f);
    return copysignf(t, x);
}

// ---------------------------------------------------------------------------
// K1: qpb[b,u] = query[b,:]@W1[:,u] + b1[u] + b2[u]
// ---------------------------------------------------------------------------
__global__ void qproj_kernel(const float* __restrict__ query,
                             const float* __restrict__ W1,
                             const float* __restrict__ b1,
                             const float* __restrict__ b2) {
    int b = blockIdx.x;
    int u = threadIdx.x;
    __shared__ float sq[D_];
    for (int i = threadIdx.x; i < D_; i += blockDim.x) sq[i] = query[b * D_ + i];
    __syncthreads();
    float acc = b1[u] + b2[u];
    #pragma unroll 8
    for (int d = 0; d < D_; d++) acc += sq[d] * W1[d * U_ + u];
    g_qpb[b * U_ + u] = acc;
}

// ---------------------------------------------------------------------------
// K2: PERSISTENT fused score + flash-context, fp16 m16n8k16 mma.
//   148 CTAs x 512 thr (16 warps, 4Mx4N, warp tile 64x32).
//   Unit = 512 seq (2 tiles x 256). Chunk = 256 rows x 32 k.
//   values: LDG float4 -> regs -> cvt fp16 -> STS (no fp32 staging).
// ---------------------------------------------------------------------------
#define AH_STR   80            // fp16 A row stride bytes (40 halfs)
#define AH_BUF_B (256 * AH_STR)        // 20480 B / buffer
#define BH_STR   528           // fp16 B row stride bytes (264 halfs)

#define OFF_E_F   1280
#define OFF_W_F   1536
#define OFF_AH_F  1600
#define OFF_BH_F  (OFF_AH_F + (2 * AH_BUF_B) / 4)   // 11840
#define SMEM_F    (OFF_BH_F + (U_ * BH_STR) / 4)    // 28736 floats
#define SMEM_SC   (SMEM_F * 4)                      // 114944 bytes

#define NTILE   2
#define KCHUNKS 8
#define NCHUNK  (NTILE * KCHUNKS)   // 16

__global__ __launch_bounds__(512, 1)
void score_mma_kernel(const float* __restrict__ values,
                      const float* __restrict__ W2,
                      const float* __restrict__ Wv,
                      const float* __restrict__ bv) {
    extern __shared__ float sm[];
    float* sQ   = sm;
    float* sWv  = sm + 128;
    float* sred = sm + 256;
    float* sE   = sm + OFF_E_F;
    float* swA  = sm + OFF_W_F;
    float* swB  = sm + OFF_W_F + 16;
    char*  sAh  = (char*)sm + OFF_AH_F * 4;
    __half* sBTh = (__half*)(sm + OFF_BH_F);

    const int tid  = threadIdx.x;
    const int wid  = tid >> 5;
    const int lane = tid & 31;
    const int g    = lane >> 2;
    const int q    = lane & 3;
    const int wm   = wid >> 2;
    const int wn   = wid & 3;
    const float bvv = bv[0];

    const uint32_t smAh_b = smem_u32(sAh);
    const uint32_t smBh_b = smem_u32(sBTh);

    // ---- one-time: B = W2^T fp16 [u][k], Wv ----
    for (int idx = tid; idx < D_ * U_; idx += 512) {
        int k = idx >> 7, u = idx & 127;
        sBTh[u * 264 + k] = __float2half_rn(W2[idx]);
    }
    for (int i = tid; i < U_; i += 512) sWv[i] = Wv[i];

    // ---- ldmatrix per-thread offsets ----
    const int a_r  = (lane & 7) + (((lane >> 3) & 1) * 8);
    const int a_kb = (lane >= 16) ? 16 : 0;
    uint32_t aoff[4];
    #pragma unroll
    for (int i = 0; i < 4; i++)
        aoff[i] = (uint32_t)((wm * 64 + i * 16 + a_r) * AH_STR + a_kb);
    const int b_r  = (lane & 7) + ((lane >= 16) ? 8 : 0);
    const int b_kb = ((lane >> 3) & 1) * 16;
    uint32_t boff[2];
    #pragma unroll
    for (int jt = 0; jt < 2; jt++)
        boff[jt] = smBh_b + (uint32_t)((wn * 32 + jt * 16 + b_r) * BH_STR + b_kb);

    const int dq = tid & 63;
    const int sh = tid >> 6;

    // per-thread copy map: 4 granules, granule = (row, f4) with idx = tid + it*512
    int crow[4], cf4[4];
    #pragma unroll
    for (int it = 0; it < 4; it++) {
        int idx = tid + it * 512;
        crow[it] = idx >> 3;
        cf4[it]  = idx & 7;
    }

    // ================= persistent unit loop =================
    for (int unit = blockIdx.x; unit < NUNIT; unit += GRID_SC) {
        const int b  = unit >> 3;
        const int ss = unit & 7;
        const int s0 = ss * 512;

        float4 va[4];
        auto ldg_chunk = [&](int gc) {
            int mm = gc >> 3, kc = gc & 7;
            const float* src = values + ((size_t)(b * S_ + s0 + mm * 256)) * D_ + kc * 32;
            #pragma unroll
            for (int it = 0; it < 4; it++)
                va[it] = *reinterpret_cast<const float4*>(
                    src + (size_t)crow[it] * D_ + cf4[it] * 4);
        };
        auto cvt_sts = [&](int gc) {
            char* abuf = sAh + (gc & 1) * AH_BUF_B;
            #pragma unroll
            for (int it = 0; it < 4; it++) {
                __half2 h0 = __floats2half2_rn(va[it].x, va[it].y);
                __half2 h1 = __floats2half2_rn(va[it].z, va[it].w);
                uint2 pk;
                pk.x = *reinterpret_cast<uint32_t*>(&h0);
                pk.y = *reinterpret_cast<uint32_t*>(&h1);
                *reinterpret_cast<uint2*>(abuf + crow[it] * AH_STR + cf4[it] * 8) = pk;
            }
        };

        // prologue: chunk 0 into buf0
        ldg_chunk(0);
        for (int i = tid; i < U_; i += 512) sQ[i] = g_qpb[b * U_ + i];
        cvt_sts(0);
        __syncthreads();

        float m_run = -1e30f, z_run = 0.0f;
        float4 c4 = make_float4(0.f, 0.f, 0.f, 0.f);

        float acc[4][4][4];

        for (int gc = 0; gc < NCHUNK; gc++) {
            if ((gc & 7) == 0) {
                #pragma unroll
                for (int i = 0; i < 4; i++)
                    #pragma unroll
                    for (int j = 0; j < 4; j++)
                        #pragma unroll
                        for (int e = 0; e < 4; e++) acc[i][j][e] = 0.0f;
            }

            if (gc + 1 < NCHUNK) ldg_chunk(gc + 1);   // hide LDG under MMA

            // ---- MMA on chunk gc (B panel at k = (gc&7)*32 -> byte offset *64) ----
            {
                uint32_t aB = smAh_b + (gc & 1) * AH_BUF_B;
                uint32_t bK = (uint32_t)((gc & 7) * 64);
                #pragma unroll
                for (int k16 = 0; k16 < 2; k16++) {
                    uint32_t a[4][4];
                    #pragma unroll
                    for (int i = 0; i < 4; i++)
                        LDSM4(a[i], aB + aoff[i] + k16 * 32);
                    uint32_t bf[2][4];
                    LDSM4(bf[0], boff[0] + bK + k16 * 32);
                    LDSM4(bf[1], boff[1] + bK + k16 * 32);
                    #pragma unroll
                    for (int j = 0; j < 4; j++) {
                        uint32_t b0 = bf[j >> 1][(j & 1) * 2];
                        uint32_t b1 = bf[j >> 1][(j & 1) * 2 + 1];
                        #pragma unroll
                        for (int i = 0; i < 4; i++)
                            mma_f16(acc[i][j], a[i], b0, b1);
                    }
                }
            }

            if (gc + 1 < NCHUNK) cvt_sts(gc + 1);     // other buffer; safe pre-barrier

            if ((gc & 7) != 7) {
                __syncthreads();
                continue;
            }

            // ======== tile epilogue (gc&7==7), mt = gc>>3 ========
            const int mt = gc >> 3;
            float p[8];
            #pragma unroll
            for (int e = 0; e < 8; e++) p[e] = 0.0f;
            #pragma unroll
            for (int i = 0; i < 4; i++)
                #pragma unroll
                for (int j = 0; j < 4; j++) {
                    int ub = wn * 32 + j * 8 + q * 2;
                    float w0 = sWv[ub], w1 = sWv[ub + 1];
                    float q0 = sQ[ub],  q1 = sQ[ub + 1];
                    p[i * 2]     += tanh_fast(acc[i][j][0] + q0) * w0
                                  + tanh_fast(acc[i][j][1] + q1) * w1;
                    p[i * 2 + 1] += tanh_fast(acc[i][j][2] + q0) * w0
                                  + tanh_fast(acc[i][j][3] + q1) * w1;
                }
            #pragma unroll
            for (int e = 0; e < 8; e++) {
                p[e] += __shfl_xor_sync(0xffffffffu, p[e], 1);
                p[e] += __shfl_xor_sync(0xffffffffu, p[e], 2);
            }
            __syncthreads();   // all MMA done; sred free; STS(gc+1) visible after
            if (q == 0) {
                float* sr = sred + wn * 256 + wm * 64;
                #pragma unroll
                for (int i = 0; i < 4; i++) {
                    sr[i * 16 + g]     = p[i * 2];
                    sr[i * 16 + g + 8] = p[i * 2 + 1];
                }
            }
            __syncthreads();

            float myscore = -1e30f;
            if (tid < 256) {
                myscore = sred[tid] + sred[256 + tid] + sred[512 + tid] + sred[768 + tid] + bvv;
                g_score[(size_t)b * S_ + s0 + mt * 256 + tid] = myscore;
            }
            float lm = myscore;
            #pragma unroll
            for (int off = 16; off > 0; off >>= 1)
                lm = fmaxf(lm, __shfl_xor_sync(0xffffffffu, lm, off));
            if (lane == 0) swA[wid] = lm;
            __syncthreads();
            float m_tile = -1e30f;
            #pragma unroll
            for (int i = 0; i < 16; i++) m_tile = fmaxf(m_tile, swA[i]);
            float m_new  = fmaxf(m_run, m_tile);
            float scale  = __expf(m_run - m_new);
            m_run = m_new;

            float e = 0.0f;
            if (tid < 256) {
                e = __expf(myscore - m_new);
                sE[tid] = e;
            }
            float ls = e;
            #pragma unroll
            for (int off = 16; off > 0; off >>= 1)
                ls += __shfl_xor_sync(0xffffffffu, ls, off);
            if (lane == 0) swB[wid] = ls;
            __syncthreads();
            float z_tile = 0.0f;
            #pragma unroll
            for (int i = 0; i < 16; i++) z_tile += swB[i];
            z_run = z_run * scale + z_tile;

            // flash context accumulation (values L2-hot)
            c4.x *= scale; c4.y *= scale; c4.z *= scale; c4.w *= scale;
            const float4* vsrc = (const float4*)(values +
                ((size_t)(b * S_ + s0 + mt * 256 + sh * 32)) * D_) + dq;
            const float* eb = sE + sh * 32;
            #pragma unroll 4
            for (int s = 0; s < 32; s++) {
                float ev = eb[s];
                float4 v = vsrc[(size_t)s * 64];
                c4.x += ev * v.x; c4.y += ev * v.y; c4.z += ev * v.z; c4.w += ev * v.w;
            }
        }

        // ---- combine 8 stripes via sred ----
        __syncthreads();
        if (sh < 4) ((float4*)sred)[sh * 64 + dq] = c4;
        __syncthreads();
        float v = 0.0f;
        if (tid < 256) {
            #pragma unroll
            for (int i = 0; i < 4; i++) v += sred[i * 256 + tid];
        }
        __syncthreads();
        if (sh >= 4) ((float4*)sred)[(sh - 4) * 64 + dq] = c4;
        __syncthreads();
        if (tid < 256) {
            #pragma unroll
            for (int i = 0; i < 4; i++) v += sred[i * 256 + tid];
            g_ctxp[(size_t)ss * B_ * D_ + b * D_ + tid] = v;
        }
        if (tid == 0) {
            g_mp[ss * B_ + b] = m_run;
            g_zp[ss * B_ + b] = z_run;
        }
        __syncthreads();
    }
}

// ---------------------------------------------------------------------------
// K3: combine flash partials -> context; derive global (m, Z).
// ---------------------------------------------------------------------------
__global__ void ctx_reduce_kernel(float* __restrict__ ctx) {
    int b = blockIdx.x;
    int d = threadIdx.x;  // 256
    float m = -1e30f;
    #pragma unroll
    for (int i = 0; i < NSPLIT; i++) m = fmaxf(m, g_mp[i * B_ + b]);
    float Z = 0.0f;
    #pragma unroll
    for (int i = 0; i < NSPLIT; i++) Z += g_zp[i * B_ + b] * __expf(g_mp[i * B_ + b] - m);
    if (d == 0) { g_MZ[b] = m; g_MZ[B_ + b] = Z; }
    float a = 0.0f;
    #pragma unroll
    for (int i = 0; i < NSPLIT; i++)
        a += g_ctxp[(size_t)i * B_ * D_ + b * D_ + d] * __expf(g_mp[i * B_ + b] - m);
    ctx[b * D_ + d] = a / Z;
}

// ---------------------------------------------------------------------------
// K4: weights[s] = exp(score[s] - m_b) / Z_b
// ---------------------------------------------------------------------------
__global__ __launch_bounds__(256)
void weights_kernel(float* __restrict__ out_w) {
    int idx = blockIdx.x * 256 + threadIdx.x;
    int b = idx >> 12;
    float m = g_MZ[b];
    float invZ = __frcp_rn(g_MZ[B_ + b]);
    out_w[idx] = __expf(g_score[idx] - m) * invZ;
}

// ---------------------------------------------------------------------------
extern "C" void kernel_launch(void* const* d_in, const int* in_sizes, int n_in,
                              void* d_out, int out_size) {
    const float* query  = (const float*)d_in[0];
    const float* values = (const float*)d_in[1];
    const float* W1     = (const float*)d_in[2];
    const float* b1     = (const float*)d_in[3];
    const float* W2     = (const float*)d_in[4];
    const float* b2     = (const float*)d_in[5];
    const float* Wv     = (const float*)d_in[6];
    const float* bv     = (const float*)d_in[7];

    float* out  = (float*)d_out;
    float* ctx  = out;
    float* wout = out + B_ * D_;

    cudaFuncSetAttribute(score_mma_kernel,
                         cudaFuncAttributeMaxDynamicSharedMemorySize, SMEM_SC);

    qproj_kernel<<<B_, U_>>>(query, W1, b1, b2);
    score_mma_kernel<<<GRID_SC, 512, SMEM_SC>>>(values, W2, Wv, bv);
    ctx_reduce_kernel<<<B_, 256>>>(ctx);
    weights_kernel<<<(B_ * S_) / 256, 256>>>(wout);
}

// round 13
// speedup vs baseline: 6.2635x; 1.0960x over previous
#include <cuda_runtime.h>
#include <cuda_fp16.h>
#include <cstdint>
#include <math.h>

#define B_ 128
#define S_ 4096
#define D_ 256
#define U_ 128

#define NSPLIT 8
#define GRID_SC 148
#define NUNIT (B_ * NSPLIT)

// ---------------- device scratch ----------------
__device__ float g_qpb[B_ * U_];
__device__ float g_score[B_ * S_];        // stores e = exp(score - M)
__device__ float g_ctxp[NSPLIT * B_ * D_];
__device__ float g_zp[NSPLIT * B_];
__device__ float g_invZ[B_];

// ---------------- helpers ----------------
__device__ __forceinline__ uint32_t smem_u32(const void* p) {
    uint32_t a;
    asm("{ .reg .u64 t; cvta.to.shared.u64 t, %1; cvt.u32.u64 %0, t; }" : "=r"(a) : "l"(p));
    return a;
}

#define LDSM4(r, addr) \
    asm volatile("ldmatrix.sync.aligned.m8n8.x4.shared.b16 {%0,%1,%2,%3}, [%4];" \
        : "=r"((r)[0]), "=r"((r)[1]), "=r"((r)[2]), "=r"((r)[3]) : "r"(addr))

// m16n8k16 fp16 MMA, fp32 accum
__device__ __forceinline__ void mma_f16(float* d, const uint32_t* a,
                                        uint32_t b0, uint32_t b1) {
    asm volatile(
        "mma.sync.aligned.m16n8k16.row.col.f32.f16.f16.f32 "
        "{%0,%1,%2,%3}, {%4,%5,%6,%7}, {%8,%9}, {%0,%1,%2,%3};"
        : "+f"(d[0]), "+f"(d[1]), "+f"(d[2]), "+f"(d[3])
        : "r"(a[0]), "r"(a[1]), "r"(a[2]), "r"(a[3]), "r"(b0), "r"(b1));
}

__device__ __forceinline__ float tanh_approx(float x) {
    float y;
    asm("tanh.approx.f32 %0, %1;" : "=f"(y) : "f"(x));
    return y;
}

// ---------------------------------------------------------------------------
// K1: qpb[b,u] = query[b,:]@W1[:,u] + b1[u] + b2[u]
// ---------------------------------------------------------------------------
__global__ void qproj_kernel(const float* __restrict__ query,
                             const float* __restrict__ W1,
                             const float* __restrict__ b1,
                             const float* __restrict__ b2) {
    int b = blockIdx.x;
    int u = threadIdx.x;
    __shared__ float sq[D_];
    for (int i = threadIdx.x; i < D_; i += blockDim.x) sq[i] = query[b * D_ + i];
    __syncthreads();
    float acc = b1[u] + b2[u];
    #pragma unroll 8
    for (int d = 0; d < D_; d++) acc += sq[d] * W1[d * U_ + u];
    g_qpb[b * U_ + u] = acc;
}

// ---------------------------------------------------------------------------
// K2: PERSISTENT fused score + context, fp16 m16n8k16 mma, fixed-shift softmax.
//   148 CTAs x 512 thr (16 warps, 4Mx4N, warp tile 64x32).
//   Unit = 512 seq (2 tiles x 256). Chunk = 256 rows x 32 k.
//   values: LDG float4 -> regs -> cvt fp16 -> STS.
//   e = exp(score - M), M = bv + sum|Wv| (exact upper bound; softmax shift-inv).
// ---------------------------------------------------------------------------
#define AH_STR   80            // fp16 A row stride bytes (40 halfs)
#define AH_BUF_B (256 * AH_STR)        // 20480 B / buffer
#define BH_STR   528           // fp16 B row stride bytes (264 halfs)

#define OFF_E_F   1280
#define OFF_W_F   1536
#define OFF_AH_F  1600
#define OFF_BH_F  (OFF_AH_F + (2 * AH_BUF_B) / 4)   // 11840
#define SMEM_F    (OFF_BH_F + (U_ * BH_STR) / 4)    // 28736 floats
#define SMEM_SC   (SMEM_F * 4)                      // 114944 bytes

#define NTILE   2
#define KCHUNKS 8
#define NCHUNK  (NTILE * KCHUNKS)   // 16

__global__ __launch_bounds__(512, 1)
void score_mma_kernel(const float* __restrict__ values,
                      const float* __restrict__ W2,
                      const float* __restrict__ Wv,
                      const float* __restrict__ bv) {
    extern __shared__ float sm[];
    float* sQ   = sm;
    float* sWv  = sm + 128;
    float* sred = sm + 256;
    float* sE   = sm + OFF_E_F;
    float* swB  = sm + OFF_W_F;
    char*  sAh  = (char*)sm + OFF_AH_F * 4;
    __half* sBTh = (__half*)(sm + OFF_BH_F);

    const int tid  = threadIdx.x;
    const int lane = tid & 31;
    const int wid  = tid >> 5;
    const int g    = lane >> 2;
    const int q    = lane & 3;
    const int wm   = wid >> 2;
    const int wn   = wid & 3;
    const float bvv = bv[0];

    const uint32_t smAh_b = smem_u32(sAh);
    const uint32_t smBh_b = smem_u32(sBTh);

    // ---- one-time: B = W2^T fp16 [u][k], Wv ----
    for (int idx = tid; idx < D_ * U_; idx += 512) {
        int k = idx >> 7, u = idx & 127;
        sBTh[u * 264 + k] = __float2half_rn(W2[idx]);
    }
    for (int i = tid; i < U_; i += 512) sWv[i] = Wv[i];
    __syncthreads();

    // fixed softmax shift: M = bv + sum|Wv|  (score <= M exactly since tanh <= 1)
    float Mfix = bvv;
    #pragma unroll 8
    for (int i = 0; i < U_; i++) Mfix += fabsf(sWv[i]);

    // ---- ldmatrix per-thread offsets ----
    const int a_r  = (lane & 7) + (((lane >> 3) & 1) * 8);
    const int a_kb = (lane >= 16) ? 16 : 0;
    uint32_t aoff[4];
    #pragma unroll
    for (int i = 0; i < 4; i++)
        aoff[i] = (uint32_t)((wm * 64 + i * 16 + a_r) * AH_STR + a_kb);
    const int b_r  = (lane & 7) + ((lane >= 16) ? 8 : 0);
    const int b_kb = ((lane >> 3) & 1) * 16;
    uint32_t boff[2];
    #pragma unroll
    for (int jt = 0; jt < 2; jt++)
        boff[jt] = smBh_b + (uint32_t)((wn * 32 + jt * 16 + b_r) * BH_STR + b_kb);

    const int dq = tid & 63;
    const int sh = tid >> 6;

    int crow[4], cf4[4];
    #pragma unroll
    for (int it = 0; it < 4; it++) {
        int idx = tid + it * 512;
        crow[it] = idx >> 3;
        cf4[it]  = idx & 7;
    }

    // ================= persistent unit loop =================
    for (int unit = blockIdx.x; unit < NUNIT; unit += GRID_SC) {
        const int b  = unit >> 3;
        const int ss = unit & 7;
        const int s0 = ss * 512;

        float4 va[4];
        auto ldg_chunk = [&](int gc) {
            int mm = gc >> 3, kc = gc & 7;
            const float* src = values + ((size_t)(b * S_ + s0 + mm * 256)) * D_ + kc * 32;
            #pragma unroll
            for (int it = 0; it < 4; it++)
                va[it] = *reinterpret_cast<const float4*>(
                    src + (size_t)crow[it] * D_ + cf4[it] * 4);
        };
        auto cvt_sts = [&](int gc) {
            char* abuf = sAh + (gc & 1) * AH_BUF_B;
            #pragma unroll
            for (int it = 0; it < 4; it++) {
                __half2 h0 = __floats2half2_rn(va[it].x, va[it].y);
                __half2 h1 = __floats2half2_rn(va[it].z, va[it].w);
                uint2 pk;
                pk.x = *reinterpret_cast<uint32_t*>(&h0);
                pk.y = *reinterpret_cast<uint32_t*>(&h1);
                *reinterpret_cast<uint2*>(abuf + crow[it] * AH_STR + cf4[it] * 8) = pk;
            }
        };

        // prologue: chunk 0 into buf0
        ldg_chunk(0);
        for (int i = tid; i < U_; i += 512) sQ[i] = g_qpb[b * U_ + i];
        cvt_sts(0);
        __syncthreads();

        float z_run = 0.0f;
        float4 c4 = make_float4(0.f, 0.f, 0.f, 0.f);

        float acc[4][4][4];

        for (int gc = 0; gc < NCHUNK; gc++) {
            if ((gc & 7) == 0) {
                #pragma unroll
                for (int i = 0; i < 4; i++)
                    #pragma unroll
                    for (int j = 0; j < 4; j++)
                        #pragma unroll
                        for (int e = 0; e < 4; e++) acc[i][j][e] = 0.0f;
            }

            if (gc + 1 < NCHUNK) ldg_chunk(gc + 1);   // hide LDG under MMA

            // ---- MMA on chunk gc ----
            {
                uint32_t aB = smAh_b + (gc & 1) * AH_BUF_B;
                uint32_t bK = (uint32_t)((gc & 7) * 64);
                #pragma unroll
                for (int k16 = 0; k16 < 2; k16++) {
                    uint32_t a[4][4];
                    #pragma unroll
                    for (int i = 0; i < 4; i++)
                        LDSM4(a[i], aB + aoff[i] + k16 * 32);
                    uint32_t bf[2][4];
                    LDSM4(bf[0], boff[0] + bK + k16 * 32);
                    LDSM4(bf[1], boff[1] + bK + k16 * 32);
                    #pragma unroll
                    for (int j = 0; j < 4; j++) {
                        uint32_t b0 = bf[j >> 1][(j & 1) * 2];
                        uint32_t b1 = bf[j >> 1][(j & 1) * 2 + 1];
                        #pragma unroll
                        for (int i = 0; i < 4; i++)
                            mma_f16(acc[i][j], a[i], b0, b1);
                    }
                }
            }

            if (gc + 1 < NCHUNK) cvt_sts(gc + 1);     // other buffer; safe pre-barrier

            if ((gc & 7) != 7) {
                __syncthreads();
                continue;
            }

            // ======== tile epilogue (gc&7==7), mt = gc>>3 ========
            const int mt = gc >> 3;
            float p[8];
            #pragma unroll
            for (int e = 0; e < 8; e++) p[e] = 0.0f;
            #pragma unroll
            for (int i = 0; i < 4; i++)
                #pragma unroll
                for (int j = 0; j < 4; j++) {
                    int ub = wn * 32 + j * 8 + q * 2;
                    float w0 = sWv[ub], w1 = sWv[ub + 1];
                    float q0 = sQ[ub],  q1 = sQ[ub + 1];
                    p[i * 2]     += tanh_approx(acc[i][j][0] + q0) * w0
                                  + tanh_approx(acc[i][j][1] + q1) * w1;
                    p[i * 2 + 1] += tanh_approx(acc[i][j][2] + q0) * w0
                                  + tanh_approx(acc[i][j][3] + q1) * w1;
                }
            #pragma unroll
            for (int e = 0; e < 8; e++) {
                p[e] += __shfl_xor_sync(0xffffffffu, p[e], 1);
                p[e] += __shfl_xor_sync(0xffffffffu, p[e], 2);
            }
            __syncthreads();   // all MMA done; sred free; STS(gc+1) visible after
            if (q == 0) {
                float* sr = sred + wn * 256 + wm * 64;
                #pragma unroll
                for (int i = 0; i < 4; i++) {
                    sr[i * 16 + g]     = p[i * 2];
                    sr[i * 16 + g + 8] = p[i * 2 + 1];
                }
            }
            __syncthreads();

            float e = 0.0f;
            if (tid < 256) {
                float myscore = sred[tid] + sred[256 + tid] + sred[512 + tid]
                              + sred[768 + tid] + bvv;
                e = __expf(myscore - Mfix);
                g_score[(size_t)b * S_ + s0 + mt * 256 + tid] = e;
                sE[tid] = e;
            }
            float ls = e;
            #pragma unroll
            for (int off = 16; off > 0; off >>= 1)
                ls += __shfl_xor_sync(0xffffffffu, ls, off);
            if (lane == 0) swB[wid] = ls;
            __syncthreads();   // swB + sE visible
            float z_tile = 0.0f;
            #pragma unroll
            for (int i = 0; i < 16; i++) z_tile += swB[i];
            z_run += z_tile;

            // context accumulation (values L2-hot, no rescale needed)
            const float4* vsrc = (const float4*)(values +
                ((size_t)(b * S_ + s0 + mt * 256 + sh * 32)) * D_) + dq;
            const float* eb = sE + sh * 32;
            #pragma unroll 4
            for (int s = 0; s < 32; s++) {
                float ev = eb[s];
                float4 v = vsrc[(size_t)s * 64];
                c4.x += ev * v.x; c4.y += ev * v.y; c4.z += ev * v.z; c4.w += ev * v.w;
            }
        }

        // ---- combine 8 stripes via sred ----
        __syncthreads();
        if (sh < 4) ((float4*)sred)[sh * 64 + dq] = c4;
        __syncthreads();
        float v = 0.0f;
        if (tid < 256) {
            #pragma unroll
            for (int i = 0; i < 4; i++) v += sred[i * 256 + tid];
        }
        __syncthreads();
        if (sh >= 4) ((float4*)sred)[(sh - 4) * 64 + dq] = c4;
        __syncthreads();
        if (tid < 256) {
            #pragma unroll
            for (int i = 0; i < 4; i++) v += sred[i * 256 + tid];
            g_ctxp[(size_t)ss * B_ * D_ + b * D_ + tid] = v;
        }
        if (tid == 0) g_zp[ss * B_ + b] = z_run;
        __syncthreads();
    }
}

// ---------------------------------------------------------------------------
// K3: combine partials -> context; Z = sum z_i (same fixed shift everywhere).
// ---------------------------------------------------------------------------
__global__ void ctx_reduce_kernel(float* __restrict__ ctx) {
    int b = blockIdx.x;
    int d = threadIdx.x;  // 256
    float Z = 0.0f;
    #pragma unroll
    for (int i = 0; i < NSPLIT; i++) Z += g_zp[i * B_ + b];
    float invZ = 1.0f / Z;
    if (d == 0) g_invZ[b] = invZ;
    float a = 0.0f;
    #pragma unroll
    for (int i = 0; i < NSPLIT; i++)
        a += g_ctxp[(size_t)i * B_ * D_ + b * D_ + d];
    ctx[b * D_ + d] = a * invZ;
}

// ---------------------------------------------------------------------------
// K4: weights = e * invZ  (g_score already holds e)
// ---------------------------------------------------------------------------
__global__ __launch_bounds__(256)
void weights_kernel(float* __restrict__ out_w) {
    int idx = blockIdx.x * 256 + threadIdx.x;
    int b = idx >> 12;
    out_w[idx] = g_score[idx] * g_invZ[b];
}

// ---------------------------------------------------------------------------
extern "C" void kernel_launch(void* const* d_in, const int* in_sizes, int n_in,
                              void* d_out, int out_size) {
    const float* query  = (const float*)d_in[0];
    const float* values = (const float*)d_in[1];
    const float* W1     = (const float*)d_in[2];
    const float* b1     = (const float*)d_in[3];
    const float* W2     = (const float*)d_in[4];
    const float* b2     = (const float*)d_in[5];
    const float* Wv     = (const float*)d_in[6];
    const float* bv     = (const float*)d_in[7];

    float* out  = (float*)d_out;
    float* ctx  = out;
    float* wout = out + B_ * D_;

    cudaFuncSetAttribute(score_mma_kernel,
                         cudaFuncAttributeMaxDynamicSharedMemorySize, SMEM_SC);

    qproj_kernel<<<B_, U_>>>(query, W1, b1, b2);
    score_mma_kernel<<<GRID_SC, 512, SMEM_SC>>>(values, W2, Wv, bv);
    ctx_reduce_kernel<<<B_, 256>>>(ctx);
    weights_kernel<<<(B_ * S_) / 256, 256>>>(wout);
}